// round 12
// baseline (speedup 1.0000x reference)
#include <cuda_runtime.h>
#include <cuda_fp16.h>
#include <cstdint>

#define B_     1024
#define G_     512
#define K_     128
#define J_     129
#define KJ_    16512
#define KE_    16640
#define KB132_ 16896        // 128 * 132 (k-blocks padded to 132)
#define KEP_   17024        // payload end: KB132_ + 128 (wimg ext)
#define KE3_   17408        // padded to 272 chunks of 64 (f16)
#define NSPLIT_ 8
#define NCH_   34           // 272 / 8
#define GSTAGES 3
#define STAGE_B 32768
#define SMEM_G (GSTAGES * STAGE_B)
#define NLS_   16

// ---------------- device scratch ----------------
__device__ float d_wrecnorm[K_];
__device__ float d_wrec2norm[J_];
__device__ float d_wnorm1[K_];
__device__ float d_q[KJ_];
__device__ float d_corr[KJ_];
__device__ float d_qp[8][KJ_];
__device__ float d_cp[8][KJ_];
__device__ float d_lg1p[NLS_][B_][K_];
__device__ float d_xpd[B_ * K_];
__device__ int   d_idx[B_];
__device__ float d_xp2d[B_ * J_];
__device__ float d_dot2[B_ * J_];
__device__ __half d_Ph[(size_t)B_ * KE3_];
__device__ __half d_w2h[(size_t)G_ * KE3_];   // pads never written -> zero-init
__device__ float d_c2[NSPLIT_][B_][G_];

// ---------------- helpers ----------------
__device__ __forceinline__ uint32_t s2u(const void* p) {
    uint32_t r;
    asm("{ .reg .u64 t; cvta.to.shared.u64 t, %1; cvt.u32.u64 %0, t; }" : "=r"(r) : "l"(p));
    return r;
}
__device__ __forceinline__ void cp16(uint32_t dst, const void* src) {
    asm volatile("cp.async.cg.shared.global [%0], [%1], 16;" :: "r"(dst), "l"(src) : "memory");
}
#define SWZ(o) ((o) ^ ((((unsigned)(o)) >> 3) & 0x70u))

__device__ __forceinline__ void mma_f16(float* c, const uint32_t* a, const uint32_t* b) {
    asm volatile(
        "mma.sync.aligned.m16n8k16.row.col.f32.f16.f16.f32 "
        "{%0,%1,%2,%3}, {%4,%5,%6,%7}, {%8,%9}, {%0,%1,%2,%3};"
        : "+f"(c[0]), "+f"(c[1]), "+f"(c[2]), "+f"(c[3])
        : "r"(a[0]), "r"(a[1]), "r"(a[2]), "r"(a[3]), "r"(b[0]), "r"(b[1]));
}
__device__ __forceinline__ void mma_tf32(float* c, const uint32_t* a, const uint32_t* b) {
    asm volatile(
        "mma.sync.aligned.m16n8k8.row.col.f32.tf32.tf32.f32 "
        "{%0,%1,%2,%3}, {%4,%5,%6,%7}, {%8,%9}, {%0,%1,%2,%3};"
        : "+f"(c[0]), "+f"(c[1]), "+f"(c[2]), "+f"(c[3])
        : "r"(a[0]), "r"(a[1]), "r"(a[2]), "r"(a[3]), "r"(b[0]), "r"(b[1]));
}
__device__ __forceinline__ unsigned div129(unsigned kj) { return (kj * 32515u) >> 22; }
__device__ __forceinline__ unsigned div132(unsigned kj) { return (kj * 31776u) >> 22; }
__device__ __forceinline__ float wmax(float v) {
#pragma unroll
    for (int o = 16; o; o >>= 1) v = fmaxf(v, __shfl_xor_sync(~0u, v, o));
    return v;
}
__device__ __forceinline__ float wsum(float v) {
#pragma unroll
    for (int o = 16; o; o >>= 1) v += __shfl_xor_sync(~0u, v, o);
    return v;
}

// ---------------- wimg2 pass (side stream) ----------------
__global__ void k_prep1(const float* __restrict__ wimg,
                        const float* __restrict__ wimg2) {
    int t = blockIdx.x * 256 + threadIdx.x;
    int gh = blockIdx.y;
    int gbeg = gh * 64;
    if (t < KJ_) {
        unsigned k = div129((unsigned)t);
        unsigned j = (unsigned)t - k * 129u;
        size_t woff = k * 132u + j;
        float q = 0.f, c = 0.f;
        for (int gg = 0; gg < 64; ++gg) {
            int g = gbeg + gg;
            float v = wimg2[(size_t)g * KJ_ + t];
            float wi = wimg[g * K_ + k];
            q += v * v;
            c += wi * v;
            d_w2h[(size_t)g * KE3_ + woff] = __float2half(v);
        }
        d_qp[gh][t] = q;
        d_cp[gh][t] = c;
    } else if (t < KE_) {
        int kk = t - KJ_;
        size_t woff = KB132_ + kk;
        for (int gg = 0; gg < 64; ++gg) {
            int g = gbeg + gg;
            d_w2h[(size_t)g * KE3_ + woff] = __float2half(wimg[g * K_ + kk]);
        }
    }
}

// reduce q/corr partials (side stream, after prep1)
__global__ void k_qred() {
    int t = blockIdx.x * 256 + threadIdx.x;
    if (t < KJ_) {
        float q = 0.f, c = 0.f;
#pragma unroll
        for (int h = 0; h < 8; ++h) { q += d_qp[h][t]; c += d_cp[h][t]; }
        d_q[t] = q;
        d_corr[t] = c;
    }
}

// ---------------- norms (main stream, cheap, unblocks latlog2) ----------------
__global__ void k_norms(const float* __restrict__ wimg,
                        const float* __restrict__ wrec,
                        const float* __restrict__ wrec2) {
    int t = threadIdx.x;
    if (t < K_) {
        float s = 0.f;
#pragma unroll 4
        for (int g = 0; g < G_; ++g) { float v = wimg[g * K_ + t]; s += v * v; }
        d_wnorm1[t] = s;
    }
    if (t < K_) {
        float s = 0.f; const float* r = wrec + t * 128;
        for (int e = 0; e < 128; ++e) s += r[e] * r[e];
        d_wrecnorm[t] = s;
    }
    if (t < J_) {
        float s = 0.f; const float* r = wrec2 + t * 128;
        for (int e = 0; e < 128; ++e) s += r[e] * r[e];
        d_wrec2norm[t] = s;
    }
}

// ---------------- logits1 via tf32 mma: grid (8 b-tiles, 16 k-splits) ----------------
__global__ __launch_bounds__(256) void k_log1t(const float* __restrict__ images,
                                               const float* __restrict__ wimg) {
    __shared__ float As[128 * 36];
    __shared__ float Bs[32 * 132];

    int tid = threadIdx.x, lane = tid & 31, wid = tid >> 5;
    int wm = wid >> 2, wn = wid & 3;
    int row_l = lane >> 2, kq = lane & 3;
    int b0 = blockIdx.x * 128, ks = blockIdx.y;
    int g0 = ks * 32;
    uint32_t asb = s2u(As), bsb = s2u(Bs);

    float acc[4][4][4];
#pragma unroll
    for (int mt = 0; mt < 4; ++mt)
#pragma unroll
        for (int nt = 0; nt < 4; ++nt)
#pragma unroll
            for (int q = 0; q < 4; ++q) acc[mt][nt][q] = 0.f;

#pragma unroll
    for (int p = 0; p < 4; ++p) {
        int i = tid + p * 256;
        int row = i >> 3, c4 = (i & 7) << 2;
        cp16(asb + (row * 36 + c4) * 4, images + (size_t)(b0 + row) * 512 + g0 + c4);
    }
#pragma unroll
    for (int p = 0; p < 4; ++p) {
        int i = tid + p * 256;
        int row = i >> 5, c4 = (i & 31) << 2;
        cp16(bsb + (row * 132 + c4) * 4, wimg + (size_t)(g0 + row) * 128 + c4);
    }
    asm volatile("cp.async.commit_group;" ::: "memory");
    asm volatile("cp.async.wait_group 0;" ::: "memory");
    __syncthreads();

#pragma unroll
    for (int kst = 0; kst < 4; ++kst) {
        uint32_t af[4][4];
#pragma unroll
        for (int mt = 0; mt < 4; ++mt) {
            int m = wm * 64 + mt * 16 + row_l;
            const float* ap = As + m * 36 + kst * 8 + kq;
            af[mt][0] = __float_as_uint(ap[0]);
            af[mt][1] = __float_as_uint(ap[8 * 36]);
            af[mt][2] = __float_as_uint(ap[4]);
            af[mt][3] = __float_as_uint(ap[8 * 36 + 4]);
        }
        uint32_t bf[4][2];
#pragma unroll
        for (int nt = 0; nt < 4; ++nt) {
            int n = wn * 32 + nt * 8 + row_l;
            const float* bp = Bs + (kst * 8 + kq) * 132 + n;
            bf[nt][0] = __float_as_uint(bp[0]);
            bf[nt][1] = __float_as_uint(bp[4 * 132]);
        }
#pragma unroll
        for (int mt = 0; mt < 4; ++mt)
#pragma unroll
            for (int nt = 0; nt < 4; ++nt)
                mma_tf32(acc[mt][nt], af[mt], bf[nt]);
    }

#pragma unroll
    for (int mt = 0; mt < 4; ++mt)
#pragma unroll
        for (int nt = 0; nt < 4; ++nt) {
            int row = b0 + wm * 64 + mt * 16 + row_l;
            int col = wn * 32 + nt * 8 + kq * 2;
            *(float2*)&d_lg1p[ks][row][col]     = make_float2(acc[mt][nt][0], acc[mt][nt][1]);
            *(float2*)&d_lg1p[ks][row + 8][col] = make_float2(acc[mt][nt][2], acc[mt][nt][3]);
        }
}

// ---------------- softmax1 -> lat -> logits2 -> softmax2+argmax (float4, stride 132) ----------------
#define SMEM_L2 ((16896 + 1024 + 1024) * 4)
__global__ void k_latlog2(const float* __restrict__ wrec) {
    extern __shared__ float sm[];
    float* wrec_s = sm;              // [128][132]
    float* xp1_s  = wrec_s + 16896;  // [8][128]
    float* lat_s  = xp1_s + 1024;    // [8][128]

    int t = threadIdx.x, lane = t & 31, w = t >> 5;
    int b = blockIdx.x * 8 + w;
    uint32_t wsb = s2u(wrec_s);

#pragma unroll
    for (int p = 0; p < 4; ++p) {
        int i = t + p * 256;
        int row = i >> 3, c4 = (i & 7) << 2;
        cp16(wsb + (row * 132 + c4) * 4, wrec + row * 128 + c4);
    }
    asm volatile("cp.async.commit_group;" ::: "memory");

    {
        float v[4];
#pragma unroll
        for (int q = 0; q < 4; ++q) {
            int k = q * 32 + lane;
            float d = 0.f;
#pragma unroll
            for (int h = 0; h < NLS_; ++h) d += d_lg1p[h][b][k];
            v[q] = (2.f * d - d_wnorm1[k]) * (1.f / 512.f);
        }
        float m = fmaxf(fmaxf(v[0], v[1]), fmaxf(v[2], v[3]));
        m = wmax(m);
        float e0 = __expf(v[0] - m), e1 = __expf(v[1] - m);
        float e2 = __expf(v[2] - m), e3 = __expf(v[3] - m);
        float s = wsum(e0 + e1 + e2 + e3);
        float inv = 1.f / s;
        xp1_s[w * 128 + lane]      = e0 * inv;
        xp1_s[w * 128 + 32 + lane] = e1 * inv;
        xp1_s[w * 128 + 64 + lane] = e2 * inv;
        xp1_s[w * 128 + 96 + lane] = e3 * inv;
    }
    asm volatile("cp.async.wait_group 0;" ::: "memory");
    __syncthreads();

    const float4* w4 = (const float4*)wrec_s;
    {
        const float4* xp4 = (const float4*)(xp1_s + w * 128);
        float4 acc = make_float4(0.f, 0.f, 0.f, 0.f);
#pragma unroll 8
        for (int k4 = 0; k4 < 32; ++k4) {
            float4 xv = xp4[k4];
            float4 w0 = w4[(4 * k4 + 0) * 33 + lane];
            float4 w1 = w4[(4 * k4 + 1) * 33 + lane];
            float4 w2 = w4[(4 * k4 + 2) * 33 + lane];
            float4 w3 = w4[(4 * k4 + 3) * 33 + lane];
            acc.x += xv.x * w0.x + xv.y * w1.x + xv.z * w2.x + xv.w * w3.x;
            acc.y += xv.x * w0.y + xv.y * w1.y + xv.z * w2.y + xv.w * w3.y;
            acc.z += xv.x * w0.z + xv.y * w1.z + xv.z * w2.z + xv.w * w3.z;
            acc.w += xv.x * w0.w + xv.y * w1.w + xv.z * w2.w + xv.w * w3.w;
        }
        *(float4*)(lat_s + w * 128 + 4 * lane) = acc;
    }
    __syncthreads();

    {
        const float4* l4 = (const float4*)(lat_s + w * 128);
        float v[4] = {0.f, 0.f, 0.f, 0.f};
#pragma unroll 4
        for (int e4 = 0; e4 < 32; ++e4) {
            float4 lv = l4[e4];
#pragma unroll
            for (int q = 0; q < 4; ++q) {
                float4 wv = w4[(lane + 32 * q) * 33 + e4];
                v[q] += lv.x * wv.x + lv.y * wv.y + lv.z * wv.z + lv.w * wv.w;
            }
        }
#pragma unroll
        for (int q = 0; q < 4; ++q) {
            int tt = lane + 32 * q;
            v[q] = (2.f * v[q] - d_wrecnorm[tt]) * (1.f / 128.f);
        }
        float bv = v[0]; int bk = lane;
#pragma unroll
        for (int q = 1; q < 4; ++q)
            if (v[q] > bv) { bv = v[q]; bk = q * 32 + lane; }
#pragma unroll
        for (int o = 16; o; o >>= 1) {
            float ov = __shfl_xor_sync(~0u, bv, o);
            int   ok = __shfl_xor_sync(~0u, bk, o);
            if (ov > bv || (ov == bv && ok < bk)) { bv = ov; bk = ok; }
        }
        if (lane == 0) d_idx[b] = bk;
        float m = bv;
        float e0 = __expf(v[0] - m), e1 = __expf(v[1] - m);
        float e2 = __expf(v[2] - m), e3 = __expf(v[3] - m);
        float s = wsum(e0 + e1 + e2 + e3);
        float inv = 1.f / s;
        d_xpd[b * 128 + lane]      = e0 * inv;
        d_xpd[b * 128 + 32 + lane] = e1 * inv;
        d_xpd[b * 128 + 64 + lane] = e2 * inv;
        d_xpd[b * 128 + 96 + lane] = e3 * inv;
    }
}

// ---------------- dot2: per-b, g-parallel, half2 (132-aligned columns) ----------------
__global__ void k_dot2(const float* __restrict__ images) {
    __shared__ float img_s[512];
    __shared__ float part[8][136];
    int b = blockIdx.x, t = threadIdx.x, lane = t & 31, w = t >> 5;
    for (int i = t; i < 512; i += 256) img_s[i] = images[b * 512 + i];
    __syncthreads();
    int idx = d_idx[b];
    const __half* colb = d_w2h + (size_t)idx * 132;
    float2 a0 = make_float2(0.f, 0.f), a1 = make_float2(0.f, 0.f);
    float a128 = 0.f;
    for (int g = w; g < 512; g += 8) {
        float iv = img_s[g];
        const __half2* rp2 = (const __half2*)(colb + (size_t)g * KE3_);
        float2 f0 = __half22float2(rp2[lane]);
        float2 f1 = __half22float2(rp2[lane + 32]);
        a0.x += iv * f0.x; a0.y += iv * f0.y;
        a1.x += iv * f1.x; a1.y += iv * f1.y;
        if (lane == 0) a128 += iv * __half2float(((const __half*)rp2)[128]);
    }
    part[w][2 * lane]     = a0.x; part[w][2 * lane + 1]  = a0.y;
    part[w][64 + 2 * lane] = a1.x; part[w][65 + 2 * lane] = a1.y;
    if (lane == 0) part[w][128] = a128;
    __syncthreads();
    if (t < 129) {
        float s = 0.f;
#pragma unroll
        for (int ww = 0; ww < 8; ++ww) s += part[ww][t];
        d_dot2[b * J_ + t] = s;
    }
}

// ---------------- softmax3 -> lat2 -> logits4 -> softmax4 (float4, stride 132) ----------------
#define SMEM_L4 ((17028 + 1056 + 1024) * 4)
__global__ void k_latlog4(const float* __restrict__ wrec2) {
    extern __shared__ float sm[];
    float* wrec2_s = sm;               // [129][132]
    float* xp2_s   = wrec2_s + 17028;  // [8][132]
    float* lat2_s  = xp2_s + 1056;     // [8][128]

    int t = threadIdx.x, lane = t & 31, w = t >> 5;
    int b = blockIdx.x * 8 + w;
    int idx = d_idx[b];
    uint32_t wsb = s2u(wrec2_s);

#pragma unroll
    for (int p = 0; p < 5; ++p) {
        int i = t + p * 256;
        if (i < 1032) {
            int row = i >> 3, c4 = (i & 7) << 2;
            cp16(wsb + (row * 132 + c4) * 4, wrec2 + row * 128 + c4);
        }
    }
    asm volatile("cp.async.commit_group;" ::: "memory");

    {
        const float* dt = d_dot2 + b * J_;
        const float* cr = d_corr + idx * J_;
        const float* qq = d_q + idx * J_;
        float v[4], v4;
#pragma unroll
        for (int q = 0; q < 4; ++q) {
            int j = q * 32 + lane;
            v[q] = (2.f * (dt[j] - cr[j]) - qq[j]) * (1.f / 512.f);
        }
        v4 = (lane == 0) ? (2.f * (dt[128] - cr[128]) - qq[128]) * (1.f / 512.f) : -INFINITY;
        float m = fmaxf(fmaxf(fmaxf(v[0], v[1]), fmaxf(v[2], v[3])), v4);
        m = wmax(m);
        float e0 = __expf(v[0] - m), e1 = __expf(v[1] - m);
        float e2 = __expf(v[2] - m), e3 = __expf(v[3] - m);
        float e4 = (lane == 0) ? __expf(v4 - m) : 0.f;
        float s = wsum(e0 + e1 + e2 + e3 + e4);
        float inv = 1.f / s;
        xp2_s[w * 132 + lane]      = e0 * inv;
        xp2_s[w * 132 + 32 + lane] = e1 * inv;
        xp2_s[w * 132 + 64 + lane] = e2 * inv;
        xp2_s[w * 132 + 96 + lane] = e3 * inv;
        if (lane == 0) xp2_s[w * 132 + 128] = e4 * inv;
    }
    asm volatile("cp.async.wait_group 0;" ::: "memory");
    __syncthreads();

    const float4* w4 = (const float4*)wrec2_s;
    {
        const float4* xp4 = (const float4*)(xp2_s + w * 132);
        float4 acc = make_float4(0.f, 0.f, 0.f, 0.f);
#pragma unroll 8
        for (int j4 = 0; j4 < 32; ++j4) {
            float4 xv = xp4[j4];
            float4 w0 = w4[(4 * j4 + 0) * 33 + lane];
            float4 w1 = w4[(4 * j4 + 1) * 33 + lane];
            float4 w2 = w4[(4 * j4 + 2) * 33 + lane];
            float4 w3 = w4[(4 * j4 + 3) * 33 + lane];
            acc.x += xv.x * w0.x + xv.y * w1.x + xv.z * w2.x + xv.w * w3.x;
            acc.y += xv.x * w0.y + xv.y * w1.y + xv.z * w2.y + xv.w * w3.y;
            acc.z += xv.x * w0.z + xv.y * w1.z + xv.z * w2.z + xv.w * w3.z;
            acc.w += xv.x * w0.w + xv.y * w1.w + xv.z * w2.w + xv.w * w3.w;
        }
        float xs = xp2_s[w * 132 + 128];
        float4 wl = w4[128 * 33 + lane];
        acc.x += xs * wl.x; acc.y += xs * wl.y; acc.z += xs * wl.z; acc.w += xs * wl.w;
        *(float4*)(lat2_s + w * 128 + 4 * lane) = acc;
    }
    __syncthreads();

    {
        const float4* l4 = (const float4*)(lat2_s + w * 128);
        float v[4] = {0.f, 0.f, 0.f, 0.f};
#pragma unroll 4
        for (int e4 = 0; e4 < 32; ++e4) {
            float4 lv = l4[e4];
#pragma unroll
            for (int q = 0; q < 4; ++q) {
                float4 wv = w4[(lane + 32 * q) * 33 + e4];
                v[q] += lv.x * wv.x + lv.y * wv.y + lv.z * wv.z + lv.w * wv.w;
            }
        }
        float v4 = -INFINITY;
        if (lane == 0) {
            float a = 0.f;
            for (int e4 = 0; e4 < 32; ++e4) {
                float4 lv = l4[e4];
                float4 wv = w4[128 * 33 + e4];
                a += lv.x * wv.x + lv.y * wv.y + lv.z * wv.z + lv.w * wv.w;
            }
            v4 = (2.f * a - d_wrec2norm[128]) * (1.f / 128.f);
        }
#pragma unroll
        for (int q = 0; q < 4; ++q) {
            int tt = lane + 32 * q;
            v[q] = (2.f * v[q] - d_wrec2norm[tt]) * (1.f / 128.f);
        }
        float m = fmaxf(fmaxf(fmaxf(v[0], v[1]), fmaxf(v[2], v[3])), v4);
        m = wmax(m);
        float e0 = __expf(v[0] - m), e1 = __expf(v[1] - m);
        float e2 = __expf(v[2] - m), e3 = __expf(v[3] - m);
        float e4 = (lane == 0) ? __expf(v4 - m) : 0.f;
        float s = wsum(e0 + e1 + e2 + e3 + e4);
        float inv = 1.f / s;
        d_xp2d[b * J_ + lane]      = e0 * inv;
        d_xp2d[b * J_ + 32 + lane] = e1 * inv;
        d_xp2d[b * J_ + 64 + lane] = e2 * inv;
        d_xp2d[b * J_ + 96 + lane] = e3 * inv;
        if (lane == 0) d_xp2d[b * J_ + 128] = e4 * inv;
    }
}

// ---------------- build P (f16, 132-block layout) ----------------
__global__ void k_buildP() {
    __shared__ float xp_s[128];
    __shared__ float xp2_s[132];
    int b = blockIdx.x, t = threadIdx.x;
    if (t < 128) xp_s[t] = d_xpd[b * 128 + t];
    if (t < 129) xp2_s[t] = d_xp2d[b * J_ + t];
    __syncthreads();
    auto pv = [&](unsigned kj) -> float {
        if (kj < KB132_) {
            unsigned k = div132(kj);
            unsigned j = kj - k * 132u;
            return (j < 129u) ? xp_s[k] * xp2_s[j] : 0.f;
        }
        if (kj < KEP_) return xp_s[kj - KB132_];
        return 0.f;
    };
    __half2* dst = (__half2*)(d_Ph + (size_t)b * KE3_);
    for (int i2 = t; i2 < KE3_ / 2; i2 += 256) {
        unsigned kj = (unsigned)i2 * 2u;
        dst[i2] = __floats2half2_rn(pv(kj), pv(kj + 1));
    }
}

// ---------------- f16 mma.sync GEMM: grid (4 g, 8 b, 8 ks), 2 CTAs/SM ----------------
__global__ __launch_bounds__(256, 2)
void k_tgemm() {
    extern __shared__ char smem[];
    uint32_t sb = s2u(smem);
    int tid = threadIdx.x;
    int lane = tid & 31, wid = tid >> 5;
    int wm = wid >> 2, wn = wid & 3;
    int row_l = lane >> 2, kq = lane & 3;
    unsigned axorm = (unsigned)row_l << 4;

    int g0 = blockIdx.x * 128, b0 = blockIdx.y * 128, ks = blockIdx.z;
    int cbase = ks * NCH_;
    const char* pbase = (const char*)(d_Ph + (size_t)b0 * KE3_);
    const char* wbase = (const char*)(d_w2h + (size_t)g0 * KE3_);

    auto fill = [&](int cl, int s) {
        int c = cbase + cl;
        uint32_t asm_ = sb + s * STAGE_B;
        uint32_t bsm = asm_ + 16384;
        const char* psrc = pbase + (size_t)c * 128;
        const char* wsrc = wbase + (size_t)c * 128;
#pragma unroll
        for (int p = 0; p < 4; ++p) {
            int i = tid + p * 256;
            int row = i >> 3;
            int cb = (i & 7) << 4;
            uint32_t sw = SWZ(row * 128 + cb);
            cp16(asm_ + sw, psrc + (size_t)row * (KE3_ * 2) + cb);
            cp16(bsm + sw, wsrc + (size_t)row * (KE3_ * 2) + cb);
        }
    };

    float acc[4][4][4];
#pragma unroll
    for (int mt = 0; mt < 4; ++mt)
#pragma unroll
        for (int nt = 0; nt < 4; ++nt)
#pragma unroll
            for (int q = 0; q < 4; ++q) acc[mt][nt][q] = 0.f;

#pragma unroll
    for (int cl = 0; cl < GSTAGES - 1; ++cl) {
        fill(cl, cl);
        asm volatile("cp.async.commit_group;" ::: "memory");
    }

    for (int it = 0; it < NCH_; ++it) {
        asm volatile("cp.async.wait_group %0;" :: "n"(GSTAGES - 2) : "memory");
        __syncthreads();

        int cf = it + GSTAGES - 1;
        if (cf < NCH_) fill(cf, cf % GSTAGES);
        asm volatile("cp.async.commit_group;" ::: "memory");

        const char* As = smem + (it % GSTAGES) * STAGE_B;
        const char* Bs = As + 16384;

#pragma unroll
        for (int kst = 0; kst < 4; ++kst) {
            uint32_t af[4][4];
#pragma unroll
            for (int mt = 0; mt < 4; ++mt) {
                unsigned m = wm * 64 + mt * 16 + row_l;
                unsigned base = m * 128 + kst * 32 + kq * 4;
                af[mt][0] = *(const uint32_t*)(As + (base ^ axorm));
                af[mt][1] = *(const uint32_t*)(As + ((base + 8 * 128) ^ axorm));
                af[mt][2] = *(const uint32_t*)(As + ((base + 16) ^ axorm));
                af[mt][3] = *(const uint32_t*)(As + ((base + 8 * 128 + 16) ^ axorm));
            }
            uint32_t bf[4][2];
#pragma unroll
            for (int nt = 0; nt < 4; ++nt) {
                unsigned n = wn * 32 + nt * 8 + row_l;
                unsigned base = n * 128 + kst * 32 + kq * 4;
                bf[nt][0] = *(const uint32_t*)(Bs + (base ^ axorm));
                bf[nt][1] = *(const uint32_t*)(Bs + ((base + 16) ^ axorm));
            }
#pragma unroll
            for (int mt = 0; mt < 4; ++mt)
#pragma unroll
                for (int nt = 0; nt < 4; ++nt)
                    mma_f16(acc[mt][nt], af[mt], bf[nt]);
        }
    }

#pragma unroll
    for (int mt = 0; mt < 4; ++mt) {
#pragma unroll
        for (int nt = 0; nt < 4; ++nt) {
            int grow = b0 + wm * 64 + mt * 16 + row_l;
            int gcol = g0 + wn * 32 + nt * 8 + kq * 2;
            *(float2*)&d_c2[ks][grow][gcol]     = make_float2(acc[mt][nt][0], acc[mt][nt][1]);
            *(float2*)&d_c2[ks][grow + 8][gcol] = make_float2(acc[mt][nt][2], acc[mt][nt][3]);
        }
    }
}

// ---------------- final loss ----------------
__global__ void k_loss(const float* __restrict__ images, float* __restrict__ out) {
    int b = blockIdx.x, t = threadIdx.x;
    float s = 0.f;
    for (int g = t; g < 512; g += 128) {
        float v = -images[b * 512 + g];
#pragma unroll
        for (int h = 0; h < NSPLIT_; ++h) v += d_c2[h][b][g];
        s += v * v;
    }
    __shared__ float red[128];
    red[t] = s; __syncthreads();
    for (int q = 64; q; q >>= 1) { if (t < q) red[t] += red[t + q]; __syncthreads(); }
    if (t == 0) out[b] = red[0] * (1.f / 512.f);
}

// ---------------- launch (fork prep1/qred onto a side stream) ----------------
static cudaStream_t g_s2 = nullptr;
static cudaEvent_t  g_evA = nullptr, g_evB = nullptr;

extern "C" void kernel_launch(void* const* d_in, const int* in_sizes, int n_in,
                              void* d_out, int out_size) {
    const float* images = (const float*)d_in[0];
    const float* wimg   = (const float*)d_in[1];
    const float* wrec   = (const float*)d_in[2];
    const float* wrec2  = (const float*)d_in[3];
    const float* wimg2  = (const float*)d_in[4];
    float* out = (float*)d_out;

    if (!g_s2) {
        cudaStreamCreateWithFlags(&g_s2, cudaStreamNonBlocking);
        cudaEventCreateWithFlags(&g_evA, cudaEventDisableTiming);
        cudaEventCreateWithFlags(&g_evB, cudaEventDisableTiming);
        cudaFuncSetAttribute(k_latlog2, cudaFuncAttributeMaxDynamicSharedMemorySize, SMEM_L2);
        cudaFuncSetAttribute(k_latlog4, cudaFuncAttributeMaxDynamicSharedMemorySize, SMEM_L4);
        cudaFuncSetAttribute(k_tgemm,   cudaFuncAttributeMaxDynamicSharedMemorySize, SMEM_G);
    }

    // fork: side stream converts wimg2 -> f16 and reduces q/corr
    cudaEventRecord(g_evA, 0);
    cudaStreamWaitEvent(g_s2, g_evA, 0);
    k_prep1<<<dim3(65, 8), 256, 0, g_s2>>>(wimg, wimg2);
    k_qred<<<65, 256, 0, g_s2>>>();
    cudaEventRecord(g_evB, g_s2);

    // main stream: encode chain (independent of prep1 until dot2)
    k_norms<<<1, 256>>>(wimg, wrec, wrec2);
    k_log1t<<<dim3(8, NLS_), 256>>>(images, wimg);
    k_latlog2<<<128, 256, SMEM_L2>>>(wrec);

    // join: dot2 needs d_w2h (side) + d_idx (main)
    cudaStreamWaitEvent(0, g_evB, 0);
    k_dot2<<<B_, 256>>>(images);
    k_latlog4<<<128, 256, SMEM_L4>>>(wrec2);
    k_buildP<<<B_, 256>>>();
    k_tgemm<<<dim3(4, 8, NSPLIT_), 256, SMEM_G>>>();
    k_loss<<<B_, 128>>>(images, out);
}

// round 13
// speedup vs baseline: 1.1085x; 1.1085x over previous
#include <cuda_runtime.h>
#include <cuda_fp16.h>
#include <cstdint>

#define B_     1024
#define G_     512
#define K_     128
#define J_     129
#define KJ_    16512
#define KE_    16640
#define KB132_ 16896        // 128 * 132 (k-blocks padded to 132)
#define KEP_   17024        // payload end: KB132_ + 128 (wimg ext)
#define KE3_   17408        // padded to 272 chunks of 64 (f16)
#define NSPLIT_ 8
#define NCH_   34           // 272 / 8
#define GSTAGES 3
#define STAGE_B 32768
#define SMEM_G (GSTAGES * STAGE_B)
#define NLS_   16

// ---------------- device scratch ----------------
__device__ float d_wrecnorm[K_];
__device__ float d_wrec2norm[J_];
__device__ float d_wnp[8][K_];        // wnorm1 partials (summed in latlog2)
__device__ float d_q[KJ_];
__device__ float d_corr[KJ_];
__device__ float d_qp[8][KJ_];
__device__ float d_cp[8][KJ_];
__device__ float d_lg1p[NLS_][B_][K_];
__device__ float d_xpd[B_ * K_];
__device__ int   d_idx[B_];
__device__ float d_xp2d[B_ * J_];
__device__ float d_dot2[B_ * J_];
__device__ __half d_Ph[(size_t)B_ * KE3_];
__device__ __half d_w2h[(size_t)G_ * KE3_];   // pads never written -> zero-init
__device__ float d_c2[NSPLIT_][B_][G_];

// ---------------- helpers ----------------
__device__ __forceinline__ uint32_t s2u(const void* p) {
    uint32_t r;
    asm("{ .reg .u64 t; cvta.to.shared.u64 t, %1; cvt.u32.u64 %0, t; }" : "=r"(r) : "l"(p));
    return r;
}
__device__ __forceinline__ void cp16(uint32_t dst, const void* src) {
    asm volatile("cp.async.cg.shared.global [%0], [%1], 16;" :: "r"(dst), "l"(src) : "memory");
}
#define SWZ(o) ((o) ^ ((((unsigned)(o)) >> 3) & 0x70u))

__device__ __forceinline__ void mma_f16(float* c, const uint32_t* a, const uint32_t* b) {
    asm volatile(
        "mma.sync.aligned.m16n8k16.row.col.f32.f16.f16.f32 "
        "{%0,%1,%2,%3}, {%4,%5,%6,%7}, {%8,%9}, {%0,%1,%2,%3};"
        : "+f"(c[0]), "+f"(c[1]), "+f"(c[2]), "+f"(c[3])
        : "r"(a[0]), "r"(a[1]), "r"(a[2]), "r"(a[3]), "r"(b[0]), "r"(b[1]));
}
__device__ __forceinline__ void mma_tf32(float* c, const uint32_t* a, const uint32_t* b) {
    asm volatile(
        "mma.sync.aligned.m16n8k8.row.col.f32.tf32.tf32.f32 "
        "{%0,%1,%2,%3}, {%4,%5,%6,%7}, {%8,%9}, {%0,%1,%2,%3};"
        : "+f"(c[0]), "+f"(c[1]), "+f"(c[2]), "+f"(c[3])
        : "r"(a[0]), "r"(a[1]), "r"(a[2]), "r"(a[3]), "r"(b[0]), "r"(b[1]));
}
__device__ __forceinline__ unsigned div129(unsigned kj) { return (kj * 32515u) >> 22; }
__device__ __forceinline__ unsigned div132(unsigned kj) { return (kj * 31776u) >> 22; }
__device__ __forceinline__ float wmax(float v) {
#pragma unroll
    for (int o = 16; o; o >>= 1) v = fmaxf(v, __shfl_xor_sync(~0u, v, o));
    return v;
}
__device__ __forceinline__ float wsum(float v) {
#pragma unroll
    for (int o = 16; o; o >>= 1) v += __shfl_xor_sync(~0u, v, o);
    return v;
}

// ---------------- wimg2 pass (side stream) ----------------
__global__ void k_prep1(const float* __restrict__ wimg,
                        const float* __restrict__ wimg2) {
    int t = blockIdx.x * 256 + threadIdx.x;
    int gh = blockIdx.y;
    int gbeg = gh * 64;
    if (t < KJ_) {
        unsigned k = div129((unsigned)t);
        unsigned j = (unsigned)t - k * 129u;
        size_t woff = k * 132u + j;
        float q = 0.f, c = 0.f;
        for (int gg = 0; gg < 64; ++gg) {
            int g = gbeg + gg;
            float v = wimg2[(size_t)g * KJ_ + t];
            float wi = wimg[g * K_ + k];
            q += v * v;
            c += wi * v;
            d_w2h[(size_t)g * KE3_ + woff] = __float2half(v);
        }
        d_qp[gh][t] = q;
        d_cp[gh][t] = c;
    } else if (t < KE_) {
        int kk = t - KJ_;
        size_t woff = KB132_ + kk;
        for (int gg = 0; gg < 64; ++gg) {
            int g = gbeg + gg;
            d_w2h[(size_t)g * KE3_ + woff] = __float2half(wimg[g * K_ + kk]);
        }
    }
}

// reduce q/corr partials (side stream, after prep1)
__global__ void k_qred() {
    int t = blockIdx.x * 256 + threadIdx.x;
    if (t < KJ_) {
        float q = 0.f, c = 0.f;
#pragma unroll
        for (int h = 0; h < 8; ++h) { q += d_qp[h][t]; c += d_cp[h][t]; }
        d_q[t] = q;
        d_corr[t] = c;
    }
}

// ---------------- wnorm1 partials (main stream, parallel) ----------------
// grid 8, block 128: block h sums wimg[g,k]^2 over g in [64h, 64h+64)
__global__ void k_wnorm(const float* __restrict__ wimg) {
    int k = threadIdx.x;
    int gbeg = blockIdx.x * 64;
    float s = 0.f;
#pragma unroll 8
    for (int gg = 0; gg < 64; ++gg) {
        float v = wimg[(gbeg + gg) * K_ + k];
        s += v * v;
    }
    d_wnp[blockIdx.x][k] = s;
}

// ---------------- wrec/wrec2 norms: warp-per-row, coalesced ----------------
__global__ void k_norms(const float* __restrict__ wrec,
                        const float* __restrict__ wrec2) {
    int t = threadIdx.x, lane = t & 31, w = t >> 5;
    // wrec rows (128): warp w handles rows w, w+8, ...
    for (int r = w; r < K_; r += 8) {
        float4 v = ((const float4*)(wrec + r * 128))[lane];
        float s = wsum(v.x * v.x + v.y * v.y + v.z * v.z + v.w * v.w);
        if (lane == 0) d_wrecnorm[r] = s;
    }
    // wrec2 rows (129)
    for (int r = w; r < J_; r += 8) {
        float4 v = ((const float4*)(wrec2 + r * 128))[lane];
        float s = wsum(v.x * v.x + v.y * v.y + v.z * v.z + v.w * v.w);
        if (lane == 0) d_wrec2norm[r] = s;
    }
}

// ---------------- logits1 via tf32 mma: grid (8 b-tiles, 16 k-splits) ----------------
__global__ __launch_bounds__(256) void k_log1t(const float* __restrict__ images,
                                               const float* __restrict__ wimg) {
    __shared__ float As[128 * 36];
    __shared__ float Bs[32 * 132];

    int tid = threadIdx.x, lane = tid & 31, wid = tid >> 5;
    int wm = wid >> 2, wn = wid & 3;
    int row_l = lane >> 2, kq = lane & 3;
    int b0 = blockIdx.x * 128, ks = blockIdx.y;
    int g0 = ks * 32;
    uint32_t asb = s2u(As), bsb = s2u(Bs);

    float acc[4][4][4];
#pragma unroll
    for (int mt = 0; mt < 4; ++mt)
#pragma unroll
        for (int nt = 0; nt < 4; ++nt)
#pragma unroll
            for (int q = 0; q < 4; ++q) acc[mt][nt][q] = 0.f;

#pragma unroll
    for (int p = 0; p < 4; ++p) {
        int i = tid + p * 256;
        int row = i >> 3, c4 = (i & 7) << 2;
        cp16(asb + (row * 36 + c4) * 4, images + (size_t)(b0 + row) * 512 + g0 + c4);
    }
#pragma unroll
    for (int p = 0; p < 4; ++p) {
        int i = tid + p * 256;
        int row = i >> 5, c4 = (i & 31) << 2;
        cp16(bsb + (row * 132 + c4) * 4, wimg + (size_t)(g0 + row) * 128 + c4);
    }
    asm volatile("cp.async.commit_group;" ::: "memory");
    asm volatile("cp.async.wait_group 0;" ::: "memory");
    __syncthreads();

#pragma unroll
    for (int kst = 0; kst < 4; ++kst) {
        uint32_t af[4][4];
#pragma unroll
        for (int mt = 0; mt < 4; ++mt) {
            int m = wm * 64 + mt * 16 + row_l;
            const float* ap = As + m * 36 + kst * 8 + kq;
            af[mt][0] = __float_as_uint(ap[0]);
            af[mt][1] = __float_as_uint(ap[8 * 36]);
            af[mt][2] = __float_as_uint(ap[4]);
            af[mt][3] = __float_as_uint(ap[8 * 36 + 4]);
        }
        uint32_t bf[4][2];
#pragma unroll
        for (int nt = 0; nt < 4; ++nt) {
            int n = wn * 32 + nt * 8 + row_l;
            const float* bp = Bs + (kst * 8 + kq) * 132 + n;
            bf[nt][0] = __float_as_uint(bp[0]);
            bf[nt][1] = __float_as_uint(bp[4 * 132]);
        }
#pragma unroll
        for (int mt = 0; mt < 4; ++mt)
#pragma unroll
            for (int nt = 0; nt < 4; ++nt)
                mma_tf32(acc[mt][nt], af[mt], bf[nt]);
    }

#pragma unroll
    for (int mt = 0; mt < 4; ++mt)
#pragma unroll
        for (int nt = 0; nt < 4; ++nt) {
            int row = b0 + wm * 64 + mt * 16 + row_l;
            int col = wn * 32 + nt * 8 + kq * 2;
            *(float2*)&d_lg1p[ks][row][col]     = make_float2(acc[mt][nt][0], acc[mt][nt][1]);
            *(float2*)&d_lg1p[ks][row + 8][col] = make_float2(acc[mt][nt][2], acc[mt][nt][3]);
        }
}

// ---------------- softmax1 -> lat -> logits2 -> softmax2+argmax (float4, stride 132) ----------------
#define SMEM_L2 ((16896 + 1024 + 1024) * 4)
__global__ void k_latlog2(const float* __restrict__ wrec) {
    extern __shared__ float sm[];
    float* wrec_s = sm;              // [128][132]
    float* xp1_s  = wrec_s + 16896;  // [8][128]
    float* lat_s  = xp1_s + 1024;    // [8][128]

    int t = threadIdx.x, lane = t & 31, w = t >> 5;
    int b = blockIdx.x * 8 + w;
    uint32_t wsb = s2u(wrec_s);

#pragma unroll
    for (int p = 0; p < 4; ++p) {
        int i = t + p * 256;
        int row = i >> 3, c4 = (i & 7) << 2;
        cp16(wsb + (row * 132 + c4) * 4, wrec + row * 128 + c4);
    }
    asm volatile("cp.async.commit_group;" ::: "memory");

    {
        float v[4];
#pragma unroll
        for (int q = 0; q < 4; ++q) {
            int k = q * 32 + lane;
            float d = 0.f;
#pragma unroll
            for (int h = 0; h < NLS_; ++h) d += d_lg1p[h][b][k];
            float wn = 0.f;
#pragma unroll
            for (int h = 0; h < 8; ++h) wn += d_wnp[h][k];
            v[q] = (2.f * d - wn) * (1.f / 512.f);
        }
        float m = fmaxf(fmaxf(v[0], v[1]), fmaxf(v[2], v[3]));
        m = wmax(m);
        float e0 = __expf(v[0] - m), e1 = __expf(v[1] - m);
        float e2 = __expf(v[2] - m), e3 = __expf(v[3] - m);
        float s = wsum(e0 + e1 + e2 + e3);
        float inv = 1.f / s;
        xp1_s[w * 128 + lane]      = e0 * inv;
        xp1_s[w * 128 + 32 + lane] = e1 * inv;
        xp1_s[w * 128 + 64 + lane] = e2 * inv;
        xp1_s[w * 128 + 96 + lane] = e3 * inv;
    }
    asm volatile("cp.async.wait_group 0;" ::: "memory");
    __syncthreads();

    const float4* w4 = (const float4*)wrec_s;
    {
        const float4* xp4 = (const float4*)(xp1_s + w * 128);
        float4 acc = make_float4(0.f, 0.f, 0.f, 0.f);
#pragma unroll 8
        for (int k4 = 0; k4 < 32; ++k4) {
            float4 xv = xp4[k4];
            float4 w0 = w4[(4 * k4 + 0) * 33 + lane];
            float4 w1 = w4[(4 * k4 + 1) * 33 + lane];
            float4 w2 = w4[(4 * k4 + 2) * 33 + lane];
            float4 w3 = w4[(4 * k4 + 3) * 33 + lane];
            acc.x += xv.x * w0.x + xv.y * w1.x + xv.z * w2.x + xv.w * w3.x;
            acc.y += xv.x * w0.y + xv.y * w1.y + xv.z * w2.y + xv.w * w3.y;
            acc.z += xv.x * w0.z + xv.y * w1.z + xv.z * w2.z + xv.w * w3.z;
            acc.w += xv.x * w0.w + xv.y * w1.w + xv.z * w2.w + xv.w * w3.w;
        }
        *(float4*)(lat_s + w * 128 + 4 * lane) = acc;
    }
    __syncthreads();

    {
        const float4* l4 = (const float4*)(lat_s + w * 128);
        float v[4] = {0.f, 0.f, 0.f, 0.f};
#pragma unroll 4
        for (int e4 = 0; e4 < 32; ++e4) {
            float4 lv = l4[e4];
#pragma unroll
            for (int q = 0; q < 4; ++q) {
                float4 wv = w4[(lane + 32 * q) * 33 + e4];
                v[q] += lv.x * wv.x + lv.y * wv.y + lv.z * wv.z + lv.w * wv.w;
            }
        }
#pragma unroll
        for (int q = 0; q < 4; ++q) {
            int tt = lane + 32 * q;
            v[q] = (2.f * v[q] - d_wrecnorm[tt]) * (1.f / 128.f);
        }
        float bv = v[0]; int bk = lane;
#pragma unroll
        for (int q = 1; q < 4; ++q)
            if (v[q] > bv) { bv = v[q]; bk = q * 32 + lane; }
#pragma unroll
        for (int o = 16; o; o >>= 1) {
            float ov = __shfl_xor_sync(~0u, bv, o);
            int   ok = __shfl_xor_sync(~0u, bk, o);
            if (ov > bv || (ov == bv && ok < bk)) { bv = ov; bk = ok; }
        }
        if (lane == 0) d_idx[b] = bk;
        float m = bv;
        float e0 = __expf(v[0] - m), e1 = __expf(v[1] - m);
        float e2 = __expf(v[2] - m), e3 = __expf(v[3] - m);
        float s = wsum(e0 + e1 + e2 + e3);
        float inv = 1.f / s;
        d_xpd[b * 128 + lane]      = e0 * inv;
        d_xpd[b * 128 + 32 + lane] = e1 * inv;
        d_xpd[b * 128 + 64 + lane] = e2 * inv;
        d_xpd[b * 128 + 96 + lane] = e3 * inv;
    }
}

// ---------------- dot2: per-b, g-parallel, half2 (132-aligned columns) ----------------
__global__ void k_dot2(const float* __restrict__ images) {
    __shared__ float img_s[512];
    __shared__ float part[8][136];
    int b = blockIdx.x, t = threadIdx.x, lane = t & 31, w = t >> 5;
    for (int i = t; i < 512; i += 256) img_s[i] = images[b * 512 + i];
    __syncthreads();
    int idx = d_idx[b];
    const __half* colb = d_w2h + (size_t)idx * 132;
    float2 a0 = make_float2(0.f, 0.f), a1 = make_float2(0.f, 0.f);
    float a128 = 0.f;
    for (int g = w; g < 512; g += 8) {
        float iv = img_s[g];
        const __half2* rp2 = (const __half2*)(colb + (size_t)g * KE3_);
        float2 f0 = __half22float2(rp2[lane]);
        float2 f1 = __half22float2(rp2[lane + 32]);
        a0.x += iv * f0.x; a0.y += iv * f0.y;
        a1.x += iv * f1.x; a1.y += iv * f1.y;
        if (lane == 0) a128 += iv * __half2float(((const __half*)rp2)[128]);
    }
    part[w][2 * lane]     = a0.x; part[w][2 * lane + 1]  = a0.y;
    part[w][64 + 2 * lane] = a1.x; part[w][65 + 2 * lane] = a1.y;
    if (lane == 0) part[w][128] = a128;
    __syncthreads();
    if (t < 129) {
        float s = 0.f;
#pragma unroll
        for (int ww = 0; ww < 8; ++ww) s += part[ww][t];
        d_dot2[b * J_ + t] = s;
    }
}

// ---------------- softmax3 -> lat2 -> logits4 -> softmax4 (float4, stride 132) ----------------
#define SMEM_L4 ((17028 + 1056 + 1024) * 4)
__global__ void k_latlog4(const float* __restrict__ wrec2) {
    extern __shared__ float sm[];
    float* wrec2_s = sm;               // [129][132]
    float* xp2_s   = wrec2_s + 17028;  // [8][132]
    float* lat2_s  = xp2_s + 1056;     // [8][128]

    int t = threadIdx.x, lane = t & 31, w = t >> 5;
    int b = blockIdx.x * 8 + w;
    int idx = d_idx[b];
    uint32_t wsb = s2u(wrec2_s);

#pragma unroll
    for (int p = 0; p < 5; ++p) {
        int i = t + p * 256;
        if (i < 1032) {
            int row = i >> 3, c4 = (i & 7) << 2;
            cp16(wsb + (row * 132 + c4) * 4, wrec2 + row * 128 + c4);
        }
    }
    asm volatile("cp.async.commit_group;" ::: "memory");

    {
        const float* dt = d_dot2 + b * J_;
        const float* cr = d_corr + idx * J_;
        const float* qq = d_q + idx * J_;
        float v[4], v4;
#pragma unroll
        for (int q = 0; q < 4; ++q) {
            int j = q * 32 + lane;
            v[q] = (2.f * (dt[j] - cr[j]) - qq[j]) * (1.f / 512.f);
        }
        v4 = (lane == 0) ? (2.f * (dt[128] - cr[128]) - qq[128]) * (1.f / 512.f) : -INFINITY;
        float m = fmaxf(fmaxf(fmaxf(v[0], v[1]), fmaxf(v[2], v[3])), v4);
        m = wmax(m);
        float e0 = __expf(v[0] - m), e1 = __expf(v[1] - m);
        float e2 = __expf(v[2] - m), e3 = __expf(v[3] - m);
        float e4 = (lane == 0) ? __expf(v4 - m) : 0.f;
        float s = wsum(e0 + e1 + e2 + e3 + e4);
        float inv = 1.f / s;
        xp2_s[w * 132 + lane]      = e0 * inv;
        xp2_s[w * 132 + 32 + lane] = e1 * inv;
        xp2_s[w * 132 + 64 + lane] = e2 * inv;
        xp2_s[w * 132 + 96 + lane] = e3 * inv;
        if (lane == 0) xp2_s[w * 132 + 128] = e4 * inv;
    }
    asm volatile("cp.async.wait_group 0;" ::: "memory");
    __syncthreads();

    const float4* w4 = (const float4*)wrec2_s;
    {
        const float4* xp4 = (const float4*)(xp2_s + w * 132);
        float4 acc = make_float4(0.f, 0.f, 0.f, 0.f);
#pragma unroll 8
        for (int j4 = 0; j4 < 32; ++j4) {
            float4 xv = xp4[j4];
            float4 w0 = w4[(4 * j4 + 0) * 33 + lane];
            float4 w1 = w4[(4 * j4 + 1) * 33 + lane];
            float4 w2 = w4[(4 * j4 + 2) * 33 + lane];
            float4 w3 = w4[(4 * j4 + 3) * 33 + lane];
            acc.x += xv.x * w0.x + xv.y * w1.x + xv.z * w2.x + xv.w * w3.x;
            acc.y += xv.x * w0.y + xv.y * w1.y + xv.z * w2.y + xv.w * w3.y;
            acc.z += xv.x * w0.z + xv.y * w1.z + xv.z * w2.z + xv.w * w3.z;
            acc.w += xv.x * w0.w + xv.y * w1.w + xv.z * w2.w + xv.w * w3.w;
        }
        float xs = xp2_s[w * 132 + 128];
        float4 wl = w4[128 * 33 + lane];
        acc.x += xs * wl.x; acc.y += xs * wl.y; acc.z += xs * wl.z; acc.w += xs * wl.w;
        *(float4*)(lat2_s + w * 128 + 4 * lane) = acc;
    }
    __syncthreads();

    {
        const float4* l4 = (const float4*)(lat2_s + w * 128);
        float v[4] = {0.f, 0.f, 0.f, 0.f};
#pragma unroll 4
        for (int e4 = 0; e4 < 32; ++e4) {
            float4 lv = l4[e4];
#pragma unroll
            for (int q = 0; q < 4; ++q) {
                float4 wv = w4[(lane + 32 * q) * 33 + e4];
                v[q] += lv.x * wv.x + lv.y * wv.y + lv.z * wv.z + lv.w * wv.w;
            }
        }
        float v4 = -INFINITY;
        if (lane == 0) {
            float a = 0.f;
            for (int e4 = 0; e4 < 32; ++e4) {
                float4 lv = l4[e4];
                float4 wv = w4[128 * 33 + e4];
                a += lv.x * wv.x + lv.y * wv.y + lv.z * wv.z + lv.w * wv.w;
            }
            v4 = (2.f * a - d_wrec2norm[128]) * (1.f / 128.f);
        }
#pragma unroll
        for (int q = 0; q < 4; ++q) {
            int tt = lane + 32 * q;
            v[q] = (2.f * v[q] - d_wrec2norm[tt]) * (1.f / 128.f);
        }
        float m = fmaxf(fmaxf(fmaxf(v[0], v[1]), fmaxf(v[2], v[3])), v4);
        m = wmax(m);
        float e0 = __expf(v[0] - m), e1 = __expf(v[1] - m);
        float e2 = __expf(v[2] - m), e3 = __expf(v[3] - m);
        float e4 = (lane == 0) ? __expf(v4 - m) : 0.f;
        float s = wsum(e0 + e1 + e2 + e3 + e4);
        float inv = 1.f / s;
        d_xp2d[b * J_ + lane]      = e0 * inv;
        d_xp2d[b * J_ + 32 + lane] = e1 * inv;
        d_xp2d[b * J_ + 64 + lane] = e2 * inv;
        d_xp2d[b * J_ + 96 + lane] = e3 * inv;
        if (lane == 0) d_xp2d[b * J_ + 128] = e4 * inv;
    }
}

// ---------------- build P (f16, 132-block layout) ----------------
__global__ void k_buildP() {
    __shared__ float xp_s[128];
    __shared__ float xp2_s[132];
    int b = blockIdx.x, t = threadIdx.x;
    if (t < 128) xp_s[t] = d_xpd[b * 128 + t];
    if (t < 129) xp2_s[t] = d_xp2d[b * J_ + t];
    __syncthreads();
    auto pv = [&](unsigned kj) -> float {
        if (kj < KB132_) {
            unsigned k = div132(kj);
            unsigned j = kj - k * 132u;
            return (j < 129u) ? xp_s[k] * xp2_s[j] : 0.f;
        }
        if (kj < KEP_) return xp_s[kj - KB132_];
        return 0.f;
    };
    __half2* dst = (__half2*)(d_Ph + (size_t)b * KE3_);
    for (int i2 = t; i2 < KE3_ / 2; i2 += 256) {
        unsigned kj = (unsigned)i2 * 2u;
        dst[i2] = __floats2half2_rn(pv(kj), pv(kj + 1));
    }
}

// ---------------- f16 mma.sync GEMM: grid (4 g, 8 b, 8 ks), 2 CTAs/SM ----------------
__global__ __launch_bounds__(256, 2)
void k_tgemm() {
    extern __shared__ char smem[];
    uint32_t sb = s2u(smem);
    int tid = threadIdx.x;
    int lane = tid & 31, wid = tid >> 5;
    int wm = wid >> 2, wn = wid & 3;
    int row_l = lane >> 2, kq = lane & 3;
    unsigned axorm = (unsigned)row_l << 4;

    int g0 = blockIdx.x * 128, b0 = blockIdx.y * 128, ks = blockIdx.z;
    int cbase = ks * NCH_;
    const char* pbase = (const char*)(d_Ph + (size_t)b0 * KE3_);
    const char* wbase = (const char*)(d_w2h + (size_t)g0 * KE3_);

    auto fill = [&](int cl, int s) {
        int c = cbase + cl;
        uint32_t asm_ = sb + s * STAGE_B;
        uint32_t bsm = asm_ + 16384;
        const char* psrc = pbase + (size_t)c * 128;
        const char* wsrc = wbase + (size_t)c * 128;
#pragma unroll
        for (int p = 0; p < 4; ++p) {
            int i = tid + p * 256;
            int row = i >> 3;
            int cb = (i & 7) << 4;
            uint32_t sw = SWZ(row * 128 + cb);
            cp16(asm_ + sw, psrc + (size_t)row * (KE3_ * 2) + cb);
            cp16(bsm + sw, wsrc + (size_t)row * (KE3_ * 2) + cb);
        }
    };

    float acc[4][4][4];
#pragma unroll
    for (int mt = 0; mt < 4; ++mt)
#pragma unroll
        for (int nt = 0; nt < 4; ++nt)
#pragma unroll
            for (int q = 0; q < 4; ++q) acc[mt][nt][q] = 0.f;

#pragma unroll
    for (int cl = 0; cl < GSTAGES - 1; ++cl) {
        fill(cl, cl);
        asm volatile("cp.async.commit_group;" ::: "memory");
    }

    for (int it = 0; it < NCH_; ++it) {
        asm volatile("cp.async.wait_group %0;" :: "n"(GSTAGES - 2) : "memory");
        __syncthreads();

        int cf = it + GSTAGES - 1;
        if (cf < NCH_) fill(cf, cf % GSTAGES);
        asm volatile("cp.async.commit_group;" ::: "memory");

        const char* As = smem + (it % GSTAGES) * STAGE_B;
        const char* Bs = As + 16384;

#pragma unroll
        for (int kst = 0; kst < 4; ++kst) {
            uint32_t af[4][4];
#pragma unroll
            for (int mt = 0; mt < 4; ++mt) {
                unsigned m = wm * 64 + mt * 16 + row_l;
                unsigned base = m * 128 + kst * 32 + kq * 4;
                af[mt][0] = *(const uint32_t*)(As + (base ^ axorm));
                af[mt][1] = *(const uint32_t*)(As + ((base + 8 * 128) ^ axorm));
                af[mt][2] = *(const uint32_t*)(As + ((base + 16) ^ axorm));
                af[mt][3] = *(const uint32_t*)(As + ((base + 8 * 128 + 16) ^ axorm));
            }
            uint32_t bf[4][2];
#pragma unroll
            for (int nt = 0; nt < 4; ++nt) {
                unsigned n = wn * 32 + nt * 8 + row_l;
                unsigned base = n * 128 + kst * 32 + kq * 4;
                bf[nt][0] = *(const uint32_t*)(Bs + (base ^ axorm));
                bf[nt][1] = *(const uint32_t*)(Bs + ((base + 16) ^ axorm));
            }
#pragma unroll
            for (int mt = 0; mt < 4; ++mt)
#pragma unroll
                for (int nt = 0; nt < 4; ++nt)
                    mma_f16(acc[mt][nt], af[mt], bf[nt]);
        }
    }

#pragma unroll
    for (int mt = 0; mt < 4; ++mt) {
#pragma unroll
        for (int nt = 0; nt < 4; ++nt) {
            int grow = b0 + wm * 64 + mt * 16 + row_l;
            int gcol = g0 + wn * 32 + nt * 8 + kq * 2;
            *(float2*)&d_c2[ks][grow][gcol]     = make_float2(acc[mt][nt][0], acc[mt][nt][1]);
            *(float2*)&d_c2[ks][grow + 8][gcol] = make_float2(acc[mt][nt][2], acc[mt][nt][3]);
        }
    }
}

// ---------------- final loss ----------------
__global__ void k_loss(const float* __restrict__ images, float* __restrict__ out) {
    int b = blockIdx.x, t = threadIdx.x;
    float s = 0.f;
    for (int g = t; g < 512; g += 128) {
        float v = -images[b * 512 + g];
#pragma unroll
        for (int h = 0; h < NSPLIT_; ++h) v += d_c2[h][b][g];
        s += v * v;
    }
    __shared__ float red[128];
    red[t] = s; __syncthreads();
    for (int q = 64; q; q >>= 1) { if (t < q) red[t] += red[t + q]; __syncthreads(); }
    if (t == 0) out[b] = red[0] * (1.f / 512.f);
}

// ---------------- launch (fork prep1/qred onto a side stream) ----------------
static cudaStream_t g_s2 = nullptr;
static cudaEvent_t  g_evA = nullptr, g_evB = nullptr;

extern "C" void kernel_launch(void* const* d_in, const int* in_sizes, int n_in,
                              void* d_out, int out_size) {
    const float* images = (const float*)d_in[0];
    const float* wimg   = (const float*)d_in[1];
    const float* wrec   = (const float*)d_in[2];
    const float* wrec2  = (const float*)d_in[3];
    const float* wimg2  = (const float*)d_in[4];
    float* out = (float*)d_out;

    if (!g_s2) {
        cudaStreamCreateWithFlags(&g_s2, cudaStreamNonBlocking);
        cudaEventCreateWithFlags(&g_evA, cudaEventDisableTiming);
        cudaEventCreateWithFlags(&g_evB, cudaEventDisableTiming);
        cudaFuncSetAttribute(k_latlog2, cudaFuncAttributeMaxDynamicSharedMemorySize, SMEM_L2);
        cudaFuncSetAttribute(k_latlog4, cudaFuncAttributeMaxDynamicSharedMemorySize, SMEM_L4);
        cudaFuncSetAttribute(k_tgemm,   cudaFuncAttributeMaxDynamicSharedMemorySize, SMEM_G);
    }

    // fork: side stream converts wimg2 -> f16 and reduces q/corr
    cudaEventRecord(g_evA, 0);
    cudaStreamWaitEvent(g_s2, g_evA, 0);
    k_prep1<<<dim3(65, 8), 256, 0, g_s2>>>(wimg, wimg2);
    k_qred<<<65, 256, 0, g_s2>>>();
    cudaEventRecord(g_evB, g_s2);

    // main stream: encode chain (independent of prep1 until dot2)
    k_wnorm<<<8, 128>>>(wimg);
    k_norms<<<1, 256>>>(wrec, wrec2);
    k_log1t<<<dim3(8, NLS_), 256>>>(images, wimg);
    k_latlog2<<<128, 256, SMEM_L2>>>(wrec);

    // join: dot2 needs d_w2h (side) + d_idx (main)
    cudaStreamWaitEvent(0, g_evB, 0);
    k_dot2<<<B_, 256>>>(images);
    k_latlog4<<<128, 256, SMEM_L4>>>(wrec2);
    k_buildP<<<B_, 256>>>();
    k_tgemm<<<dim3(4, 8, NSPLIT_), 256, SMEM_G>>>();
    k_loss<<<B_, 128>>>(images, out);
}

// round 16
// speedup vs baseline: 1.1496x; 1.0371x over previous
#include <cuda_runtime.h>
#include <cuda_fp16.h>
#include <cstdint>

#define B_     1024
#define G_     512
#define K_     128
#define J_     129
#define KJ_    16512
#define KE_    16640
#define KB132_ 16896        // 128 * 132 (k-blocks padded to 132)
#define KEP_   17024        // payload end: KB132_ + 128 (wimg ext)
#define KE3_   17408        // padded to 272 chunks of 64 (f16)
#define NSPLIT_ 8
#define NCH_   34           // 272 / 8
#define GSTAGES 3
#define STAGE_B 32768
#define SMEM_G (GSTAGES * STAGE_B)
#define NLS_   16

// ---------------- device scratch ----------------
__device__ float d_wrecnorm[K_];
__device__ float d_wrec2norm[J_];
__device__ float d_wnp[8][K_];
__device__ float d_q[KJ_];
__device__ float d_corr[KJ_];
__device__ float d_qp[8][KJ_];
__device__ float d_cp[8][KJ_];
__device__ float d_lg1p[NLS_][B_][K_];
__device__ float d_xpd[B_ * K_];
__device__ int   d_idx[B_];
__device__ float d_xp2d[B_ * J_];
__device__ float d_dot2[B_ * J_];
__device__ __half d_Ph[(size_t)B_ * KE3_];
__device__ __half d_w2h[(size_t)G_ * KE3_];   // pads never written -> zero-init
__device__ float d_c2[NSPLIT_][B_][G_];

// ---------------- helpers ----------------
__device__ __forceinline__ uint32_t s2u(const void* p) {
    uint32_t r;
    asm("{ .reg .u64 t; cvta.to.shared.u64 t, %1; cvt.u32.u64 %0, t; }" : "=r"(r) : "l"(p));
    return r;
}
__device__ __forceinline__ void cp16(uint32_t dst, const void* src) {
    asm volatile("cp.async.cg.shared.global [%0], [%1], 16;" :: "r"(dst), "l"(src) : "memory");
}
#define SWZ(o) ((o) ^ ((((unsigned)(o)) >> 3) & 0x70u))

__device__ __forceinline__ void mma_f16(float* c, const uint32_t* a, const uint32_t* b) {
    asm volatile(
        "mma.sync.aligned.m16n8k16.row.col.f32.f16.f16.f32 "
        "{%0,%1,%2,%3}, {%4,%5,%6,%7}, {%8,%9}, {%0,%1,%2,%3};"
        : "+f"(c[0]), "+f"(c[1]), "+f"(c[2]), "+f"(c[3])
        : "r"(a[0]), "r"(a[1]), "r"(a[2]), "r"(a[3]), "r"(b[0]), "r"(b[1]));
}
__device__ __forceinline__ void mma_tf32(float* c, const uint32_t* a, const uint32_t* b) {
    asm volatile(
        "mma.sync.aligned.m16n8k8.row.col.f32.tf32.tf32.f32 "
        "{%0,%1,%2,%3}, {%4,%5,%6,%7}, {%8,%9}, {%0,%1,%2,%3};"
        : "+f"(c[0]), "+f"(c[1]), "+f"(c[2]), "+f"(c[3])
        : "r"(a[0]), "r"(a[1]), "r"(a[2]), "r"(a[3]), "r"(b[0]), "r"(b[1]));
}
__device__ __forceinline__ unsigned div129(unsigned kj) { return (kj * 32515u) >> 22; }
__device__ __forceinline__ unsigned div132(unsigned kj) { return (kj * 31776u) >> 22; }
__device__ __forceinline__ float wmax(float v) {
#pragma unroll
    for (int o = 16; o; o >>= 1) v = fmaxf(v, __shfl_xor_sync(~0u, v, o));
    return v;
}
__device__ __forceinline__ float wsum(float v) {
#pragma unroll
    for (int o = 16; o; o >>= 1) v += __shfl_xor_sync(~0u, v, o);
    return v;
}

// ---------------- wimg2 pass ----------------
__global__ void k_prep1(const float* __restrict__ wimg,
                        const float* __restrict__ wimg2) {
    int t = blockIdx.x * 256 + threadIdx.x;
    int gh = blockIdx.y;
    int gbeg = gh * 64;
    if (t < KJ_) {
        unsigned k = div129((unsigned)t);
        unsigned j = (unsigned)t - k * 129u;
        size_t woff = k * 132u + j;
        float q = 0.f, c = 0.f;
        for (int gg = 0; gg < 64; ++gg) {
            int g = gbeg + gg;
            float v = wimg2[(size_t)g * KJ_ + t];
            float wi = wimg[g * K_ + k];
            q += v * v;
            c += wi * v;
            d_w2h[(size_t)g * KE3_ + woff] = __float2half(v);
        }
        d_qp[gh][t] = q;
        d_cp[gh][t] = c;
    } else if (t < KE_) {
        int kk = t - KJ_;
        size_t woff = KB132_ + kk;
        for (int gg = 0; gg < 64; ++gg) {
            int g = gbeg + gg;
            d_w2h[(size_t)g * KE3_ + woff] = __float2half(wimg[g * K_ + kk]);
        }
    }
}

// reduce q/corr partials
__global__ void k_qred() {
    int t = blockIdx.x * 256 + threadIdx.x;
    if (t < KJ_) {
        float q = 0.f, c = 0.f;
#pragma unroll
        for (int h = 0; h < 8; ++h) { q += d_qp[h][t]; c += d_cp[h][t]; }
        d_q[t] = q;
        d_corr[t] = c;
    }
}

// ---------------- wnorm1 partials: grid 8, block 128 ----------------
__global__ void k_wnorm(const float* __restrict__ wimg) {
    int k = threadIdx.x;
    int gbeg = blockIdx.x * 64;
    float s = 0.f;
#pragma unroll 8
    for (int gg = 0; gg < 64; ++gg) {
        float v = wimg[(gbeg + gg) * K_ + k];
        s += v * v;
    }
    d_wnp[blockIdx.x][k] = s;
}

// ---------------- wrec/wrec2 norms: one warp per row, grid 33 ----------------
__global__ void k_norms(const float* __restrict__ wrec,
                        const float* __restrict__ wrec2) {
    int lane = threadIdx.x & 31;
    int r = blockIdx.x * 8 + (threadIdx.x >> 5);
    if (r < K_) {
        float4 v = ((const float4*)(wrec + r * 128))[lane];
        float s = wsum(v.x * v.x + v.y * v.y + v.z * v.z + v.w * v.w);
        if (lane == 0) d_wrecnorm[r] = s;
    } else if (r < K_ + J_) {
        int r2 = r - K_;
        float4 v = ((const float4*)(wrec2 + r2 * 128))[lane];
        float s = wsum(v.x * v.x + v.y * v.y + v.z * v.z + v.w * v.w);
        if (lane == 0) d_wrec2norm[r2] = s;
    }
}

// ---------------- logits1 via tf32 mma: grid (8 b-tiles, 16 k-splits) ----------------
__global__ __launch_bounds__(256) void k_log1t(const float* __restrict__ images,
                                               const float* __restrict__ wimg) {
    __shared__ float As[128 * 36];
    __shared__ float Bs[32 * 132];

    int tid = threadIdx.x, lane = tid & 31, wid = tid >> 5;
    int wm = wid >> 2, wn = wid & 3;
    int row_l = lane >> 2, kq = lane & 3;
    int b0 = blockIdx.x * 128, ks = blockIdx.y;
    int g0 = ks * 32;
    uint32_t asb = s2u(As), bsb = s2u(Bs);

    float acc[4][4][4];
#pragma unroll
    for (int mt = 0; mt < 4; ++mt)
#pragma unroll
        for (int nt = 0; nt < 4; ++nt)
#pragma unroll
            for (int q = 0; q < 4; ++q) acc[mt][nt][q] = 0.f;

#pragma unroll
    for (int p = 0; p < 4; ++p) {
        int i = tid + p * 256;
        int row = i >> 3, c4 = (i & 7) << 2;
        cp16(asb + (row * 36 + c4) * 4, images + (size_t)(b0 + row) * 512 + g0 + c4);
    }
#pragma unroll
    for (int p = 0; p < 4; ++p) {
        int i = tid + p * 256;
        int row = i >> 5, c4 = (i & 31) << 2;
        cp16(bsb + (row * 132 + c4) * 4, wimg + (size_t)(g0 + row) * 128 + c4);
    }
    asm volatile("cp.async.commit_group;" ::: "memory");
    asm volatile("cp.async.wait_group 0;" ::: "memory");
    __syncthreads();

#pragma unroll
    for (int kst = 0; kst < 4; ++kst) {
        uint32_t af[4][4];
#pragma unroll
        for (int mt = 0; mt < 4; ++mt) {
            int m = wm * 64 + mt * 16 + row_l;
            const float* ap = As + m * 36 + kst * 8 + kq;
            af[mt][0] = __float_as_uint(ap[0]);
            af[mt][1] = __float_as_uint(ap[8 * 36]);
            af[mt][2] = __float_as_uint(ap[4]);
            af[mt][3] = __float_as_uint(ap[8 * 36 + 4]);
        }
        uint32_t bf[4][2];
#pragma unroll
        for (int nt = 0; nt < 4; ++nt) {
            int n = wn * 32 + nt * 8 + row_l;
            const float* bp = Bs + (kst * 8 + kq) * 132 + n;
            bf[nt][0] = __float_as_uint(bp[0]);
            bf[nt][1] = __float_as_uint(bp[4 * 132]);
        }
#pragma unroll
        for (int mt = 0; mt < 4; ++mt)
#pragma unroll
            for (int nt = 0; nt < 4; ++nt)
                mma_tf32(acc[mt][nt], af[mt], bf[nt]);
    }

#pragma unroll
    for (int mt = 0; mt < 4; ++mt)
#pragma unroll
        for (int nt = 0; nt < 4; ++nt) {
            int row = b0 + wm * 64 + mt * 16 + row_l;
            int col = wn * 32 + nt * 8 + kq * 2;
            *(float2*)&d_lg1p[ks][row][col]     = make_float2(acc[mt][nt][0], acc[mt][nt][1]);
            *(float2*)&d_lg1p[ks][row + 8][col] = make_float2(acc[mt][nt][2], acc[mt][nt][3]);
        }
}

// ---------------- softmax1 -> lat -> logits2 -> softmax2+argmax (float4, stride 132) ----------------
#define SMEM_L2 ((16896 + 1024 + 1024) * 4)
__global__ void k_latlog2(const float* __restrict__ wrec) {
    extern __shared__ float sm[];
    float* wrec_s = sm;              // [128][132]
    float* xp1_s  = wrec_s + 16896;  // [8][128]
    float* lat_s  = xp1_s + 1024;    // [8][128]

    int t = threadIdx.x, lane = t & 31, w = t >> 5;
    int b = blockIdx.x * 8 + w;
    uint32_t wsb = s2u(wrec_s);

#pragma unroll
    for (int p = 0; p < 4; ++p) {
        int i = t + p * 256;
        int row = i >> 3, c4 = (i & 7) << 2;
        cp16(wsb + (row * 132 + c4) * 4, wrec + row * 128 + c4);
    }
    asm volatile("cp.async.commit_group;" ::: "memory");

    {
        float v[4];
#pragma unroll
        for (int q = 0; q < 4; ++q) {
            int k = q * 32 + lane;
            float d = 0.f;
#pragma unroll
            for (int h = 0; h < NLS_; ++h) d += d_lg1p[h][b][k];
            float wn = 0.f;
#pragma unroll
            for (int h = 0; h < 8; ++h) wn += d_wnp[h][k];
            v[q] = (2.f * d - wn) * (1.f / 512.f);
        }
        float m = fmaxf(fmaxf(v[0], v[1]), fmaxf(v[2], v[3]));
        m = wmax(m);
        float e0 = __expf(v[0] - m), e1 = __expf(v[1] - m);
        float e2 = __expf(v[2] - m), e3 = __expf(v[3] - m);
        float s = wsum(e0 + e1 + e2 + e3);
        float inv = 1.f / s;
        xp1_s[w * 128 + lane]      = e0 * inv;
        xp1_s[w * 128 + 32 + lane] = e1 * inv;
        xp1_s[w * 128 + 64 + lane] = e2 * inv;
        xp1_s[w * 128 + 96 + lane] = e3 * inv;
    }
    asm volatile("cp.async.wait_group 0;" ::: "memory");
    __syncthreads();

    const float4* w4 = (const float4*)wrec_s;
    {
        const float4* xp4 = (const float4*)(xp1_s + w * 128);
        float4 acc = make_float4(0.f, 0.f, 0.f, 0.f);
#pragma unroll 8
        for (int k4 = 0; k4 < 32; ++k4) {
            float4 xv = xp4[k4];
            float4 w0 = w4[(4 * k4 + 0) * 33 + lane];
            float4 w1 = w4[(4 * k4 + 1) * 33 + lane];
            float4 w2 = w4[(4 * k4 + 2) * 33 + lane];
            float4 w3 = w4[(4 * k4 + 3) * 33 + lane];
            acc.x += xv.x * w0.x + xv.y * w1.x + xv.z * w2.x + xv.w * w3.x;
            acc.y += xv.x * w0.y + xv.y * w1.y + xv.z * w2.y + xv.w * w3.y;
            acc.z += xv.x * w0.z + xv.y * w1.z + xv.z * w2.z + xv.w * w3.z;
            acc.w += xv.x * w0.w + xv.y * w1.w + xv.z * w2.w + xv.w * w3.w;
        }
        *(float4*)(lat_s + w * 128 + 4 * lane) = acc;
    }
    __syncthreads();

    {
        const float4* l4 = (const float4*)(lat_s + w * 128);
        float v[4] = {0.f, 0.f, 0.f, 0.f};
#pragma unroll 4
        for (int e4 = 0; e4 < 32; ++e4) {
            float4 lv = l4[e4];
#pragma unroll
            for (int q = 0; q < 4; ++q) {
                float4 wv = w4[(lane + 32 * q) * 33 + e4];
                v[q] += lv.x * wv.x + lv.y * wv.y + lv.z * wv.z + lv.w * wv.w;
            }
        }
#pragma unroll
        for (int q = 0; q < 4; ++q) {
            int tt = lane + 32 * q;
            v[q] = (2.f * v[q] - d_wrecnorm[tt]) * (1.f / 128.f);
        }
        float bv = v[0]; int bk = lane;
#pragma unroll
        for (int q = 1; q < 4; ++q)
            if (v[q] > bv) { bv = v[q]; bk = q * 32 + lane; }
#pragma unroll
        for (int o = 16; o; o >>= 1) {
            float ov = __shfl_xor_sync(~0u, bv, o);
            int   ok = __shfl_xor_sync(~0u, bk, o);
            if (ov > bv || (ov == bv && ok < bk)) { bv = ov; bk = ok; }
        }
        if (lane == 0) d_idx[b] = bk;
        float m = bv;
        float e0 = __expf(v[0] - m), e1 = __expf(v[1] - m);
        float e2 = __expf(v[2] - m), e3 = __expf(v[3] - m);
        float s = wsum(e0 + e1 + e2 + e3);
        float inv = 1.f / s;
        d_xpd[b * 128 + lane]      = e0 * inv;
        d_xpd[b * 128 + 32 + lane] = e1 * inv;
        d_xpd[b * 128 + 64 + lane] = e2 * inv;
        d_xpd[b * 128 + 96 + lane] = e3 * inv;
    }
}

// ---------------- dot2: per-b, g-parallel, half2 (132-aligned columns) ----------------
__global__ void k_dot2(const float* __restrict__ images) {
    __shared__ float img_s[512];
    __shared__ float part[8][136];
    int b = blockIdx.x, t = threadIdx.x, lane = t & 31, w = t >> 5;
    for (int i = t; i < 512; i += 256) img_s[i] = images[b * 512 + i];
    __syncthreads();
    int idx = d_idx[b];
    const __half* colb = d_w2h + (size_t)idx * 132;
    float2 a0 = make_float2(0.f, 0.f), a1 = make_float2(0.f, 0.f);
    float a128 = 0.f;
    for (int g = w; g < 512; g += 8) {
        float iv = img_s[g];
        const __half2* rp2 = (const __half2*)(colb + (size_t)g * KE3_);
        float2 f0 = __half22float2(rp2[lane]);
        float2 f1 = __half22float2(rp2[lane + 32]);
        a0.x += iv * f0.x; a0.y += iv * f0.y;
        a1.x += iv * f1.x; a1.y += iv * f1.y;
        if (lane == 0) a128 += iv * __half2float(((const __half*)rp2)[128]);
    }
    part[w][2 * lane]     = a0.x; part[w][2 * lane + 1]  = a0.y;
    part[w][64 + 2 * lane] = a1.x; part[w][65 + 2 * lane] = a1.y;
    if (lane == 0) part[w][128] = a128;
    __syncthreads();
    if (t < 129) {
        float s = 0.f;
#pragma unroll
        for (int ww = 0; ww < 8; ++ww) s += part[ww][t];
        d_dot2[b * J_ + t] = s;
    }
}

// ---------------- softmax3 -> lat2 -> logits4 -> softmax4 (float4, stride 132) ----------------
#define SMEM_L4 ((17028 + 1056 + 1024) * 4)
__global__ void k_latlog4(const float* __restrict__ wrec2) {
    extern __shared__ float sm[];
    float* wrec2_s = sm;               // [129][132]
    float* xp2_s   = wrec2_s + 17028;  // [8][132]
    float* lat2_s  = xp2_s + 1056;     // [8][128]

    int t = threadIdx.x, lane = t & 31, w = t >> 5;
    int b = blockIdx.x * 8 + w;
    int idx = d_idx[b];
    uint32_t wsb = s2u(wrec2_s);

#pragma unroll
    for (int p = 0; p < 5; ++p) {
        int i = t + p * 256;
        if (i < 1032) {
            int row = i >> 3, c4 = (i & 7) << 2;
            cp16(wsb + (row * 132 + c4) * 4, wrec2 + row * 128 + c4);
        }
    }
    asm volatile("cp.async.commit_group;" ::: "memory");

    {
        const float* dt = d_dot2 + b * J_;
        const float* cr = d_corr + idx * J_;
        const float* qq = d_q + idx * J_;
        float v[4], v4;
#pragma unroll
        for (int q = 0; q < 4; ++q) {
            int j = q * 32 + lane;
            v[q] = (2.f * (dt[j] - cr[j]) - qq[j]) * (1.f / 512.f);
        }
        v4 = (lane == 0) ? (2.f * (dt[128] - cr[128]) - qq[128]) * (1.f / 512.f) : -INFINITY;
        float m = fmaxf(fmaxf(fmaxf(v[0], v[1]), fmaxf(v[2], v[3])), v4);
        m = wmax(m);
        float e0 = __expf(v[0] - m), e1 = __expf(v[1] - m);
        float e2 = __expf(v[2] - m), e3 = __expf(v[3] - m);
        float e4 = (lane == 0) ? __expf(v4 - m) : 0.f;
        float s = wsum(e0 + e1 + e2 + e3 + e4);
        float inv = 1.f / s;
        xp2_s[w * 132 + lane]      = e0 * inv;
        xp2_s[w * 132 + 32 + lane] = e1 * inv;
        xp2_s[w * 132 + 64 + lane] = e2 * inv;
        xp2_s[w * 132 + 96 + lane] = e3 * inv;
        if (lane == 0) xp2_s[w * 132 + 128] = e4 * inv;
    }
    asm volatile("cp.async.wait_group 0;" ::: "memory");
    __syncthreads();

    const float4* w4 = (const float4*)wrec2_s;
    {
        const float4* xp4 = (const float4*)(xp2_s + w * 132);
        float4 acc = make_float4(0.f, 0.f, 0.f, 0.f);
#pragma unroll 8
        for (int j4 = 0; j4 < 32; ++j4) {
            float4 xv = xp4[j4];
            float4 w0 = w4[(4 * j4 + 0) * 33 + lane];
            float4 w1 = w4[(4 * j4 + 1) * 33 + lane];
            float4 w2 = w4[(4 * j4 + 2) * 33 + lane];
            float4 w3 = w4[(4 * j4 + 3) * 33 + lane];
            acc.x += xv.x * w0.x + xv.y * w1.x + xv.z * w2.x + xv.w * w3.x;
            acc.y += xv.x * w0.y + xv.y * w1.y + xv.z * w2.y + xv.w * w3.y;
            acc.z += xv.x * w0.z + xv.y * w1.z + xv.z * w2.z + xv.w * w3.z;
            acc.w += xv.x * w0.w + xv.y * w1.w + xv.z * w2.w + xv.w * w3.w;
        }
        float xs = xp2_s[w * 132 + 128];
        float4 wl = w4[128 * 33 + lane];
        acc.x += xs * wl.x; acc.y += xs * wl.y; acc.z += xs * wl.z; acc.w += xs * wl.w;
        *(float4*)(lat2_s + w * 128 + 4 * lane) = acc;
    }
    __syncthreads();

    {
        const float4* l4 = (const float4*)(lat2_s + w * 128);
        float v[4] = {0.f, 0.f, 0.f, 0.f};
#pragma unroll 4
        for (int e4 = 0; e4 < 32; ++e4) {
            float4 lv = l4[e4];
#pragma unroll
            for (int q = 0; q < 4; ++q) {
                float4 wv = w4[(lane + 32 * q) * 33 + e4];
                v[q] += lv.x * wv.x + lv.y * wv.y + lv.z * wv.z + lv.w * wv.w;
            }
        }
        float v4 = -INFINITY;
        if (lane == 0) {
            float a = 0.f;
            for (int e4 = 0; e4 < 32; ++e4) {
                float4 lv = l4[e4];
                float4 wv = w4[128 * 33 + e4];
                a += lv.x * wv.x + lv.y * wv.y + lv.z * wv.z + lv.w * wv.w;
            }
            v4 = (2.f * a - d_wrec2norm[128]) * (1.f / 128.f);
        }
#pragma unroll
        for (int q = 0; q < 4; ++q) {
            int tt = lane + 32 * q;
            v[q] = (2.f * v[q] - d_wrec2norm[tt]) * (1.f / 128.f);
        }
        float m = fmaxf(fmaxf(fmaxf(v[0], v[1]), fmaxf(v[2], v[3])), v4);
        m = wmax(m);
        float e0 = __expf(v[0] - m), e1 = __expf(v[1] - m);
        float e2 = __expf(v[2] - m), e3 = __expf(v[3] - m);
        float e4 = (lane == 0) ? __expf(v4 - m) : 0.f;
        float s = wsum(e0 + e1 + e2 + e3 + e4);
        float inv = 1.f / s;
        d_xp2d[b * J_ + lane]      = e0 * inv;
        d_xp2d[b * J_ + 32 + lane] = e1 * inv;
        d_xp2d[b * J_ + 64 + lane] = e2 * inv;
        d_xp2d[b * J_ + 96 + lane] = e3 * inv;
        if (lane == 0) d_xp2d[b * J_ + 128] = e4 * inv;
    }
}

// ---------------- build P (f16, 132-block layout) ----------------
__global__ void k_buildP() {
    __shared__ float xp_s[128];
    __shared__ float xp2_s[132];
    int b = blockIdx.x, t = threadIdx.x;
    if (t < 128) xp_s[t] = d_xpd[b * 128 + t];
    if (t < 129) xp2_s[t] = d_xp2d[b * J_ + t];
    __syncthreads();
    auto pv = [&](unsigned kj) -> float {
        if (kj < KB132_) {
            unsigned k = div132(kj);
            unsigned j = kj - k * 132u;
            return (j < 129u) ? xp_s[k] * xp2_s[j] : 0.f;
        }
        if (kj < KEP_) return xp_s[kj - KB132_];
        return 0.f;
    };
    __half2* dst = (__half2*)(d_Ph + (size_t)b * KE3_);
    for (int i2 = t; i2 < KE3_ / 2; i2 += 256) {
        unsigned kj = (unsigned)i2 * 2u;
        dst[i2] = __floats2half2_rn(pv(kj), pv(kj + 1));
    }
}

// ---------------- f16 mma.sync GEMM: grid (4 g, 8 b, 8 ks), 2 CTAs/SM ----------------
__global__ __launch_bounds__(256, 2)
void k_tgemm() {
    extern __shared__ char smem[];
    uint32_t sb = s2u(smem);
    int tid = threadIdx.x;
    int lane = tid & 31, wid = tid >> 5;
    int wm = wid >> 2, wn = wid & 3;
    int row_l = lane >> 2, kq = lane & 3;
    unsigned axorm = (unsigned)row_l << 4;

    int g0 = blockIdx.x * 128, b0 = blockIdx.y * 128, ks = blockIdx.z;
    int cbase = ks * NCH_;
    const char* pbase = (const char*)(d_Ph + (size_t)b0 * KE3_);
    const char* wbase = (const char*)(d_w2h + (size_t)g0 * KE3_);

    auto fill = [&](int cl, int s) {
        int c = cbase + cl;
        uint32_t asm_ = sb + s * STAGE_B;
        uint32_t bsm = asm_ + 16384;
        const char* psrc = pbase + (size_t)c * 128;
        const char* wsrc = wbase + (size_t)c * 128;
#pragma unroll
        for (int p = 0; p < 4; ++p) {
            int i = tid + p * 256;
            int row = i >> 3;
            int cb = (i & 7) << 4;
            uint32_t sw = SWZ(row * 128 + cb);
            cp16(asm_ + sw, psrc + (size_t)row * (KE3_ * 2) + cb);
            cp16(bsm + sw, wsrc + (size_t)row * (KE3_ * 2) + cb);
        }
    };

    float acc[4][4][4];
#pragma unroll
    for (int mt = 0; mt < 4; ++mt)
#pragma unroll
        for (int nt = 0; nt < 4; ++nt)
#pragma unroll
            for (int q = 0; q < 4; ++q) acc[mt][nt][q] = 0.f;

#pragma unroll
    for (int cl = 0; cl < GSTAGES - 1; ++cl) {
        fill(cl, cl);
        asm volatile("cp.async.commit_group;" ::: "memory");
    }

    for (int it = 0; it < NCH_; ++it) {
        asm volatile("cp.async.wait_group %0;" :: "n"(GSTAGES - 2) : "memory");
        __syncthreads();

        int cf = it + GSTAGES - 1;
        if (cf < NCH_) fill(cf, cf % GSTAGES);
        asm volatile("cp.async.commit_group;" ::: "memory");

        const char* As = smem + (it % GSTAGES) * STAGE_B;
        const char* Bs = As + 16384;

#pragma unroll
        for (int kst = 0; kst < 4; ++kst) {
            uint32_t af[4][4];
#pragma unroll
            for (int mt = 0; mt < 4; ++mt) {
                unsigned m = wm * 64 + mt * 16 + row_l;
                unsigned base = m * 128 + kst * 32 + kq * 4;
                af[mt][0] = *(const uint32_t*)(As + (base ^ axorm));
                af[mt][1] = *(const uint32_t*)(As + ((base + 8 * 128) ^ axorm));
                af[mt][2] = *(const uint32_t*)(As + ((base + 16) ^ axorm));
                af[mt][3] = *(const uint32_t*)(As + ((base + 8 * 128 + 16) ^ axorm));
            }
            uint32_t bf[4][2];
#pragma unroll
            for (int nt = 0; nt < 4; ++nt) {
                unsigned n = wn * 32 + nt * 8 + row_l;
                unsigned base = n * 128 + kst * 32 + kq * 4;
                bf[nt][0] = *(const uint32_t*)(Bs + (base ^ axorm));
                bf[nt][1] = *(const uint32_t*)(Bs + ((base + 16) ^ axorm));
            }
#pragma unroll
            for (int mt = 0; mt < 4; ++mt)
#pragma unroll
                for (int nt = 0; nt < 4; ++nt)
                    mma_f16(acc[mt][nt], af[mt], bf[nt]);
        }
    }

#pragma unroll
    for (int mt = 0; mt < 4; ++mt) {
#pragma unroll
        for (int nt = 0; nt < 4; ++nt) {
            int grow = b0 + wm * 64 + mt * 16 + row_l;
            int gcol = g0 + wn * 32 + nt * 8 + kq * 2;
            *(float2*)&d_c2[ks][grow][gcol]     = make_float2(acc[mt][nt][0], acc[mt][nt][1]);
            *(float2*)&d_c2[ks][grow + 8][gcol] = make_float2(acc[mt][nt][2], acc[mt][nt][3]);
        }
    }
}

// ---------------- final loss ----------------
__global__ void k_loss(const float* __restrict__ images, float* __restrict__ out) {
    int b = blockIdx.x, t = threadIdx.x;
    float s = 0.f;
    for (int g = t; g < 512; g += 128) {
        float v = -images[b * 512 + g];
#pragma unroll
        for (int h = 0; h < NSPLIT_; ++h) v += d_c2[h][b][g];
        s += v * v;
    }
    __shared__ float red[128];
    red[t] = s; __syncthreads();
    for (int q = 64; q; q >>= 1) { if (t < q) red[t] += red[t + q]; __syncthreads(); }
    if (t == 0) out[b] = red[0] * (1.f / 512.f);
}

// ---------------- launch: strictly sequential, default stream, no statics ----------------
extern "C" void kernel_launch(void* const* d_in, const int* in_sizes, int n_in,
                              void* d_out, int out_size) {
    const float* images = (const float*)d_in[0];
    const float* wimg   = (const float*)d_in[1];
    const float* wrec   = (const float*)d_in[2];
    const float* wrec2  = (const float*)d_in[3];
    const float* wimg2  = (const float*)d_in[4];
    float* out = (float*)d_out;

    cudaFuncSetAttribute(k_latlog2, cudaFuncAttributeMaxDynamicSharedMemorySize, SMEM_L2);
    cudaFuncSetAttribute(k_latlog4, cudaFuncAttributeMaxDynamicSharedMemorySize, SMEM_L4);
    cudaFuncSetAttribute(k_tgemm,   cudaFuncAttributeMaxDynamicSharedMemorySize, SMEM_G);

    k_prep1<<<dim3(65, 8), 256>>>(wimg, wimg2);
    k_qred<<<65, 256>>>();
    k_wnorm<<<8, 128>>>(wimg);
    k_norms<<<33, 256>>>(wrec, wrec2);
    k_log1t<<<dim3(8, NLS_), 256>>>(images, wimg);
    k_latlog2<<<128, 256, SMEM_L2>>>(wrec);
    k_dot2<<<B_, 256>>>(images);
    k_latlog4<<<128, 256, SMEM_L4>>>(wrec2);
    k_buildP<<<B_, 256>>>();
    k_tgemm<<<dim3(4, 8, NSPLIT_), 256, SMEM_G>>>();
    k_loss<<<B_, 128>>>(images, out);
}

// round 17
// speedup vs baseline: 1.2612x; 1.0971x over previous
#include <cuda_runtime.h>
#include <cuda_fp16.h>
#include <cstdint>

#define B_     1024
#define G_     512
#define K_     128
#define J_     129
#define KJ_    16512
#define KE_    16640
#define KB132_ 16896        // 128 * 132 (k-blocks padded to 132)
#define KEP_   17024        // payload end: KB132_ + 128 (wimg ext)
#define KE3_   17408        // padded to 272 chunks of 64 (f16)
#define NSPLIT_ 8
#define NCH_   34           // 272 / 8
#define GSTAGES 3
#define STAGE_B 32768
#define SMEM_G (GSTAGES * STAGE_B)
#define NLS_   16

// ---------------- device scratch ----------------
__device__ float d_wrecnorm[K_];
__device__ float d_wrec2norm[J_];
__device__ float d_wnp[8][K_];
__device__ float d_q[KJ_];
__device__ float d_corr[KJ_];
__device__ float d_qp[8][KJ_];
__device__ float d_cp[8][KJ_];
__device__ float d_lg1p[NLS_][B_][K_];
__device__ float d_xpd[B_ * K_];
__device__ int   d_idx[B_];
__device__ float d_xp2d[B_ * J_];
__device__ float d_dot2[B_ * J_];
__device__ __half d_Ph[(size_t)B_ * KE3_];
__device__ __half d_w2h[(size_t)G_ * KE3_];   // pads never written -> zero-init
__device__ float d_c2[NSPLIT_][B_][G_];

// ---------------- helpers ----------------
__device__ __forceinline__ uint32_t s2u(const void* p) {
    uint32_t r;
    asm("{ .reg .u64 t; cvta.to.shared.u64 t, %1; cvt.u32.u64 %0, t; }" : "=r"(r) : "l"(p));
    return r;
}
__device__ __forceinline__ void cp16(uint32_t dst, const void* src) {
    asm volatile("cp.async.cg.shared.global [%0], [%1], 16;" :: "r"(dst), "l"(src) : "memory");
}
#define SWZ(o) ((o) ^ ((((unsigned)(o)) >> 3) & 0x70u))

__device__ __forceinline__ void mma_f16(float* c, const uint32_t* a, const uint32_t* b) {
    asm volatile(
        "mma.sync.aligned.m16n8k16.row.col.f32.f16.f16.f32 "
        "{%0,%1,%2,%3}, {%4,%5,%6,%7}, {%8,%9}, {%0,%1,%2,%3};"
        : "+f"(c[0]), "+f"(c[1]), "+f"(c[2]), "+f"(c[3])
        : "r"(a[0]), "r"(a[1]), "r"(a[2]), "r"(a[3]), "r"(b[0]), "r"(b[1]));
}
__device__ __forceinline__ void mma_tf32(float* c, const uint32_t* a, const uint32_t* b) {
    asm volatile(
        "mma.sync.aligned.m16n8k8.row.col.f32.tf32.tf32.f32 "
        "{%0,%1,%2,%3}, {%4,%5,%6,%7}, {%8,%9}, {%0,%1,%2,%3};"
        : "+f"(c[0]), "+f"(c[1]), "+f"(c[2]), "+f"(c[3])
        : "r"(a[0]), "r"(a[1]), "r"(a[2]), "r"(a[3]), "r"(b[0]), "r"(b[1]));
}
__device__ __forceinline__ void ldsm_x4(uint32_t* r, uint32_t addr) {
    asm volatile("ldmatrix.sync.aligned.m8n8.x4.shared.b16 {%0,%1,%2,%3}, [%4];"
        : "=r"(r[0]), "=r"(r[1]), "=r"(r[2]), "=r"(r[3]) : "r"(addr));
}
__device__ __forceinline__ unsigned div129(unsigned kj) { return (kj * 32515u) >> 22; }
__device__ __forceinline__ unsigned div132(unsigned kj) { return (kj * 31776u) >> 22; }
__device__ __forceinline__ float wmax(float v) {
#pragma unroll
    for (int o = 16; o; o >>= 1) v = fmaxf(v, __shfl_xor_sync(~0u, v, o));
    return v;
}
__device__ __forceinline__ float wsum(float v) {
#pragma unroll
    for (int o = 16; o; o >>= 1) v += __shfl_xor_sync(~0u, v, o);
    return v;
}

// ---------------- wimg2 pass ----------------
__global__ void k_prep1(const float* __restrict__ wimg,
                        const float* __restrict__ wimg2) {
    int t = blockIdx.x * 256 + threadIdx.x;
    int gh = blockIdx.y;
    int gbeg = gh * 64;
    if (t < KJ_) {
        unsigned k = div129((unsigned)t);
        unsigned j = (unsigned)t - k * 129u;
        size_t woff = k * 132u + j;
        float q = 0.f, c = 0.f;
#pragma unroll 4
        for (int gg = 0; gg < 64; ++gg) {
            int g = gbeg + gg;
            float v = wimg2[(size_t)g * KJ_ + t];
            float wi = wimg[g * K_ + k];
            q += v * v;
            c += wi * v;
            d_w2h[(size_t)g * KE3_ + woff] = __float2half(v);
        }
        d_qp[gh][t] = q;
        d_cp[gh][t] = c;
    } else if (t < KE_) {
        int kk = t - KJ_;
        size_t woff = KB132_ + kk;
#pragma unroll 4
        for (int gg = 0; gg < 64; ++gg) {
            int g = gbeg + gg;
            d_w2h[(size_t)g * KE3_ + woff] = __float2half(wimg[g * K_ + kk]);
        }
    }
}

// reduce q/corr partials
__global__ void k_qred() {
    int t = blockIdx.x * 256 + threadIdx.x;
    if (t < KJ_) {
        float q = 0.f, c = 0.f;
#pragma unroll
        for (int h = 0; h < 8; ++h) { q += d_qp[h][t]; c += d_cp[h][t]; }
        d_q[t] = q;
        d_corr[t] = c;
    }
}

// ---------------- wnorm1 partials: grid 8, block 128 ----------------
__global__ void k_wnorm(const float* __restrict__ wimg) {
    int k = threadIdx.x;
    int gbeg = blockIdx.x * 64;
    float s = 0.f;
#pragma unroll 8
    for (int gg = 0; gg < 64; ++gg) {
        float v = wimg[(gbeg + gg) * K_ + k];
        s += v * v;
    }
    d_wnp[blockIdx.x][k] = s;
}

// ---------------- wrec/wrec2 norms: one warp per row, grid 33 ----------------
__global__ void k_norms(const float* __restrict__ wrec,
                        const float* __restrict__ wrec2) {
    int lane = threadIdx.x & 31;
    int r = blockIdx.x * 8 + (threadIdx.x >> 5);
    if (r < K_) {
        float4 v = ((const float4*)(wrec + r * 128))[lane];
        float s = wsum(v.x * v.x + v.y * v.y + v.z * v.z + v.w * v.w);
        if (lane == 0) d_wrecnorm[r] = s;
    } else if (r < K_ + J_) {
        int r2 = r - K_;
        float4 v = ((const float4*)(wrec2 + r2 * 128))[lane];
        float s = wsum(v.x * v.x + v.y * v.y + v.z * v.z + v.w * v.w);
        if (lane == 0) d_wrec2norm[r2] = s;
    }
}

// ---------------- logits1 via tf32 mma: grid (8 b-tiles, 16 k-splits) ----------------
__global__ __launch_bounds__(256) void k_log1t(const float* __restrict__ images,
                                               const float* __restrict__ wimg) {
    __shared__ float As[128 * 36];
    __shared__ float Bs[32 * 132];

    int tid = threadIdx.x, lane = tid & 31, wid = tid >> 5;
    int wm = wid >> 2, wn = wid & 3;
    int row_l = lane >> 2, kq = lane & 3;
    int b0 = blockIdx.x * 128, ks = blockIdx.y;
    int g0 = ks * 32;
    uint32_t asb = s2u(As), bsb = s2u(Bs);

    float acc[4][4][4];
#pragma unroll
    for (int mt = 0; mt < 4; ++mt)
#pragma unroll
        for (int nt = 0; nt < 4; ++nt)
#pragma unroll
            for (int q = 0; q < 4; ++q) acc[mt][nt][q] = 0.f;

#pragma unroll
    for (int p = 0; p < 4; ++p) {
        int i = tid + p * 256;
        int row = i >> 3, c4 = (i & 7) << 2;
        cp16(asb + (row * 36 + c4) * 4, images + (size_t)(b0 + row) * 512 + g0 + c4);
    }
#pragma unroll
    for (int p = 0; p < 4; ++p) {
        int i = tid + p * 256;
        int row = i >> 5, c4 = (i & 31) << 2;
        cp16(bsb + (row * 132 + c4) * 4, wimg + (size_t)(g0 + row) * 128 + c4);
    }
    asm volatile("cp.async.commit_group;" ::: "memory");
    asm volatile("cp.async.wait_group 0;" ::: "memory");
    __syncthreads();

#pragma unroll
    for (int kst = 0; kst < 4; ++kst) {
        uint32_t af[4][4];
#pragma unroll
        for (int mt = 0; mt < 4; ++mt) {
            int m = wm * 64 + mt * 16 + row_l;
            const float* ap = As + m * 36 + kst * 8 + kq;
            af[mt][0] = __float_as_uint(ap[0]);
            af[mt][1] = __float_as_uint(ap[8 * 36]);
            af[mt][2] = __float_as_uint(ap[4]);
            af[mt][3] = __float_as_uint(ap[8 * 36 + 4]);
        }
        uint32_t bf[4][2];
#pragma unroll
        for (int nt = 0; nt < 4; ++nt) {
            int n = wn * 32 + nt * 8 + row_l;
            const float* bp = Bs + (kst * 8 + kq) * 132 + n;
            bf[nt][0] = __float_as_uint(bp[0]);
            bf[nt][1] = __float_as_uint(bp[4 * 132]);
        }
#pragma unroll
        for (int mt = 0; mt < 4; ++mt)
#pragma unroll
            for (int nt = 0; nt < 4; ++nt)
                mma_tf32(acc[mt][nt], af[mt], bf[nt]);
    }

#pragma unroll
    for (int mt = 0; mt < 4; ++mt)
#pragma unroll
        for (int nt = 0; nt < 4; ++nt) {
            int row = b0 + wm * 64 + mt * 16 + row_l;
            int col = wn * 32 + nt * 8 + kq * 2;
            *(float2*)&d_lg1p[ks][row][col]     = make_float2(acc[mt][nt][0], acc[mt][nt][1]);
            *(float2*)&d_lg1p[ks][row + 8][col] = make_float2(acc[mt][nt][2], acc[mt][nt][3]);
        }
}

// ---------------- softmax1 -> lat -> logits2 -> softmax2+argmax (float4, stride 132) ----------------
#define SMEM_L2 ((16896 + 1024 + 1024) * 4)
__global__ void k_latlog2(const float* __restrict__ wrec) {
    extern __shared__ float sm[];
    float* wrec_s = sm;              // [128][132]
    float* xp1_s  = wrec_s + 16896;  // [8][128]
    float* lat_s  = xp1_s + 1024;    // [8][128]

    int t = threadIdx.x, lane = t & 31, w = t >> 5;
    int b = blockIdx.x * 8 + w;
    uint32_t wsb = s2u(wrec_s);

#pragma unroll
    for (int p = 0; p < 4; ++p) {
        int i = t + p * 256;
        int row = i >> 3, c4 = (i & 7) << 2;
        cp16(wsb + (row * 132 + c4) * 4, wrec + row * 128 + c4);
    }
    asm volatile("cp.async.commit_group;" ::: "memory");

    {
        float v[4];
#pragma unroll
        for (int q = 0; q < 4; ++q) {
            int k = q * 32 + lane;
            float d = 0.f;
#pragma unroll
            for (int h = 0; h < NLS_; ++h) d += d_lg1p[h][b][k];
            float wn = 0.f;
#pragma unroll
            for (int h = 0; h < 8; ++h) wn += d_wnp[h][k];
            v[q] = (2.f * d - wn) * (1.f / 512.f);
        }
        float m = fmaxf(fmaxf(v[0], v[1]), fmaxf(v[2], v[3]));
        m = wmax(m);
        float e0 = __expf(v[0] - m), e1 = __expf(v[1] - m);
        float e2 = __expf(v[2] - m), e3 = __expf(v[3] - m);
        float s = wsum(e0 + e1 + e2 + e3);
        float inv = 1.f / s;
        xp1_s[w * 128 + lane]      = e0 * inv;
        xp1_s[w * 128 + 32 + lane] = e1 * inv;
        xp1_s[w * 128 + 64 + lane] = e2 * inv;
        xp1_s[w * 128 + 96 + lane] = e3 * inv;
    }
    asm volatile("cp.async.wait_group 0;" ::: "memory");
    __syncthreads();

    const float4* w4 = (const float4*)wrec_s;
    {
        const float4* xp4 = (const float4*)(xp1_s + w * 128);
        float4 acc = make_float4(0.f, 0.f, 0.f, 0.f);
#pragma unroll 8
        for (int k4 = 0; k4 < 32; ++k4) {
            float4 xv = xp4[k4];
            float4 w0 = w4[(4 * k4 + 0) * 33 + lane];
            float4 w1 = w4[(4 * k4 + 1) * 33 + lane];
            float4 w2 = w4[(4 * k4 + 2) * 33 + lane];
            float4 w3 = w4[(4 * k4 + 3) * 33 + lane];
            acc.x += xv.x * w0.x + xv.y * w1.x + xv.z * w2.x + xv.w * w3.x;
            acc.y += xv.x * w0.y + xv.y * w1.y + xv.z * w2.y + xv.w * w3.y;
            acc.z += xv.x * w0.z + xv.y * w1.z + xv.z * w2.z + xv.w * w3.z;
            acc.w += xv.x * w0.w + xv.y * w1.w + xv.z * w2.w + xv.w * w3.w;
        }
        *(float4*)(lat_s + w * 128 + 4 * lane) = acc;
    }
    __syncthreads();

    {
        const float4* l4 = (const float4*)(lat_s + w * 128);
        float v[4] = {0.f, 0.f, 0.f, 0.f};
#pragma unroll 4
        for (int e4 = 0; e4 < 32; ++e4) {
            float4 lv = l4[e4];
#pragma unroll
            for (int q = 0; q < 4; ++q) {
                float4 wv = w4[(lane + 32 * q) * 33 + e4];
                v[q] += lv.x * wv.x + lv.y * wv.y + lv.z * wv.z + lv.w * wv.w;
            }
        }
#pragma unroll
        for (int q = 0; q < 4; ++q) {
            int tt = lane + 32 * q;
            v[q] = (2.f * v[q] - d_wrecnorm[tt]) * (1.f / 128.f);
        }
        float bv = v[0]; int bk = lane;
#pragma unroll
        for (int q = 1; q < 4; ++q)
            if (v[q] > bv) { bv = v[q]; bk = q * 32 + lane; }
#pragma unroll
        for (int o = 16; o; o >>= 1) {
            float ov = __shfl_xor_sync(~0u, bv, o);
            int   ok = __shfl_xor_sync(~0u, bk, o);
            if (ov > bv || (ov == bv && ok < bk)) { bv = ov; bk = ok; }
        }
        if (lane == 0) d_idx[b] = bk;
        float m = bv;
        float e0 = __expf(v[0] - m), e1 = __expf(v[1] - m);
        float e2 = __expf(v[2] - m), e3 = __expf(v[3] - m);
        float s = wsum(e0 + e1 + e2 + e3);
        float inv = 1.f / s;
        d_xpd[b * 128 + lane]      = e0 * inv;
        d_xpd[b * 128 + 32 + lane] = e1 * inv;
        d_xpd[b * 128 + 64 + lane] = e2 * inv;
        d_xpd[b * 128 + 96 + lane] = e3 * inv;
    }
}

// ---------------- dot2: per-b, g-parallel, half2 (132-aligned columns) ----------------
__global__ void k_dot2(const float* __restrict__ images) {
    __shared__ float img_s[512];
    __shared__ float part[8][136];
    int b = blockIdx.x, t = threadIdx.x, lane = t & 31, w = t >> 5;
    for (int i = t; i < 512; i += 256) img_s[i] = images[b * 512 + i];
    __syncthreads();
    int idx = d_idx[b];
    const __half* colb = d_w2h + (size_t)idx * 132;
    float2 a0 = make_float2(0.f, 0.f), a1 = make_float2(0.f, 0.f);
    float a128 = 0.f;
    for (int g = w; g < 512; g += 8) {
        float iv = img_s[g];
        const __half2* rp2 = (const __half2*)(colb + (size_t)g * KE3_);
        float2 f0 = __half22float2(rp2[lane]);
        float2 f1 = __half22float2(rp2[lane + 32]);
        a0.x += iv * f0.x; a0.y += iv * f0.y;
        a1.x += iv * f1.x; a1.y += iv * f1.y;
        if (lane == 0) a128 += iv * __half2float(((const __half*)rp2)[128]);
    }
    part[w][2 * lane]     = a0.x; part[w][2 * lane + 1]  = a0.y;
    part[w][64 + 2 * lane] = a1.x; part[w][65 + 2 * lane] = a1.y;
    if (lane == 0) part[w][128] = a128;
    __syncthreads();
    if (t < 129) {
        float s = 0.f;
#pragma unroll
        for (int ww = 0; ww < 8; ++ww) s += part[ww][t];
        d_dot2[b * J_ + t] = s;
    }
}

// ---------------- softmax3 -> lat2 -> logits4 -> softmax4 (float4, stride 132) ----------------
#define SMEM_L4 ((17028 + 1056 + 1024) * 4)
__global__ void k_latlog4(const float* __restrict__ wrec2) {
    extern __shared__ float sm[];
    float* wrec2_s = sm;               // [129][132]
    float* xp2_s   = wrec2_s + 17028;  // [8][132]
    float* lat2_s  = xp2_s + 1056;     // [8][128]

    int t = threadIdx.x, lane = t & 31, w = t >> 5;
    int b = blockIdx.x * 8 + w;
    int idx = d_idx[b];
    uint32_t wsb = s2u(wrec2_s);

#pragma unroll
    for (int p = 0; p < 5; ++p) {
        int i = t + p * 256;
        if (i < 1032) {
            int row = i >> 3, c4 = (i & 7) << 2;
            cp16(wsb + (row * 132 + c4) * 4, wrec2 + row * 128 + c4);
        }
    }
    asm volatile("cp.async.commit_group;" ::: "memory");

    {
        const float* dt = d_dot2 + b * J_;
        const float* cr = d_corr + idx * J_;
        const float* qq = d_q + idx * J_;
        float v[4], v4;
#pragma unroll
        for (int q = 0; q < 4; ++q) {
            int j = q * 32 + lane;
            v[q] = (2.f * (dt[j] - cr[j]) - qq[j]) * (1.f / 512.f);
        }
        v4 = (lane == 0) ? (2.f * (dt[128] - cr[128]) - qq[128]) * (1.f / 512.f) : -INFINITY;
        float m = fmaxf(fmaxf(fmaxf(v[0], v[1]), fmaxf(v[2], v[3])), v4);
        m = wmax(m);
        float e0 = __expf(v[0] - m), e1 = __expf(v[1] - m);
        float e2 = __expf(v[2] - m), e3 = __expf(v[3] - m);
        float e4 = (lane == 0) ? __expf(v4 - m) : 0.f;
        float s = wsum(e0 + e1 + e2 + e3 + e4);
        float inv = 1.f / s;
        xp2_s[w * 132 + lane]      = e0 * inv;
        xp2_s[w * 132 + 32 + lane] = e1 * inv;
        xp2_s[w * 132 + 64 + lane] = e2 * inv;
        xp2_s[w * 132 + 96 + lane] = e3 * inv;
        if (lane == 0) xp2_s[w * 132 + 128] = e4 * inv;
    }
    asm volatile("cp.async.wait_group 0;" ::: "memory");
    __syncthreads();

    const float4* w4 = (const float4*)wrec2_s;
    {
        const float4* xp4 = (const float4*)(xp2_s + w * 132);
        float4 acc = make_float4(0.f, 0.f, 0.f, 0.f);
#pragma unroll 8
        for (int j4 = 0; j4 < 32; ++j4) {
            float4 xv = xp4[j4];
            float4 w0 = w4[(4 * j4 + 0) * 33 + lane];
            float4 w1 = w4[(4 * j4 + 1) * 33 + lane];
            float4 w2 = w4[(4 * j4 + 2) * 33 + lane];
            float4 w3 = w4[(4 * j4 + 3) * 33 + lane];
            acc.x += xv.x * w0.x + xv.y * w1.x + xv.z * w2.x + xv.w * w3.x;
            acc.y += xv.x * w0.y + xv.y * w1.y + xv.z * w2.y + xv.w * w3.y;
            acc.z += xv.x * w0.z + xv.y * w1.z + xv.z * w2.z + xv.w * w3.z;
            acc.w += xv.x * w0.w + xv.y * w1.w + xv.z * w2.w + xv.w * w3.w;
        }
        float xs = xp2_s[w * 132 + 128];
        float4 wl = w4[128 * 33 + lane];
        acc.x += xs * wl.x; acc.y += xs * wl.y; acc.z += xs * wl.z; acc.w += xs * wl.w;
        *(float4*)(lat2_s + w * 128 + 4 * lane) = acc;
    }
    __syncthreads();

    {
        const float4* l4 = (const float4*)(lat2_s + w * 128);
        float v[4] = {0.f, 0.f, 0.f, 0.f};
#pragma unroll 4
        for (int e4 = 0; e4 < 32; ++e4) {
            float4 lv = l4[e4];
#pragma unroll
            for (int q = 0; q < 4; ++q) {
                float4 wv = w4[(lane + 32 * q) * 33 + e4];
                v[q] += lv.x * wv.x + lv.y * wv.y + lv.z * wv.z + lv.w * wv.w;
            }
        }
        float v4 = -INFINITY;
        if (lane == 0) {
            float a = 0.f;
            for (int e4 = 0; e4 < 32; ++e4) {
                float4 lv = l4[e4];
                float4 wv = w4[128 * 33 + e4];
                a += lv.x * wv.x + lv.y * wv.y + lv.z * wv.z + lv.w * wv.w;
            }
            v4 = (2.f * a - d_wrec2norm[128]) * (1.f / 128.f);
        }
#pragma unroll
        for (int q = 0; q < 4; ++q) {
            int tt = lane + 32 * q;
            v[q] = (2.f * v[q] - d_wrec2norm[tt]) * (1.f / 128.f);
        }
        float m = fmaxf(fmaxf(fmaxf(v[0], v[1]), fmaxf(v[2], v[3])), v4);
        m = wmax(m);
        float e0 = __expf(v[0] - m), e1 = __expf(v[1] - m);
        float e2 = __expf(v[2] - m), e3 = __expf(v[3] - m);
        float e4 = (lane == 0) ? __expf(v4 - m) : 0.f;
        float s = wsum(e0 + e1 + e2 + e3 + e4);
        float inv = 1.f / s;
        d_xp2d[b * J_ + lane]      = e0 * inv;
        d_xp2d[b * J_ + 32 + lane] = e1 * inv;
        d_xp2d[b * J_ + 64 + lane] = e2 * inv;
        d_xp2d[b * J_ + 96 + lane] = e3 * inv;
        if (lane == 0) d_xp2d[b * J_ + 128] = e4 * inv;
    }
}

// ---------------- build P (f16, 132-block layout) ----------------
__global__ void k_buildP() {
    __shared__ float xp_s[128];
    __shared__ float xp2_s[132];
    int b = blockIdx.x, t = threadIdx.x;
    if (t < 128) xp_s[t] = d_xpd[b * 128 + t];
    if (t < 129) xp2_s[t] = d_xp2d[b * J_ + t];
    __syncthreads();
    auto pv = [&](unsigned kj) -> float {
        if (kj < KB132_) {
            unsigned k = div132(kj);
            unsigned j = kj - k * 132u;
            return (j < 129u) ? xp_s[k] * xp2_s[j] : 0.f;
        }
        if (kj < KEP_) return xp_s[kj - KB132_];
        return 0.f;
    };
    __half2* dst = (__half2*)(d_Ph + (size_t)b * KE3_);
    for (int i2 = t; i2 < KE3_ / 2; i2 += 256) {
        unsigned kj = (unsigned)i2 * 2u;
        dst[i2] = __floats2half2_rn(pv(kj), pv(kj + 1));
    }
}

// ---------------- f16 mma.sync GEMM with ldmatrix: grid (4 g, 8 b, 8 ks), 2 CTAs/SM ----------------
__global__ __launch_bounds__(256, 2)
void k_tgemm() {
    extern __shared__ char smem[];
    uint32_t sb = s2u(smem);
    int tid = threadIdx.x;
    int lane = tid & 31, wid = tid >> 5;
    int wm = wid >> 2, wn = wid & 3;
    int row_l = lane >> 2, kq = lane & 3;

    // ldmatrix lane address components
    int rA = lane & 15;                              // A: row offset within 16
    int bA = (lane & 16) ? 16 : 0;                   // A: k-chunk byte select
    int rB = (lane & 7) + ((lane & 16) ? 8 : 0);     // B: n-row offset within 16
    int bB = (lane & 8) ? 16 : 0;                    // B: k-chunk byte select

    int g0 = blockIdx.x * 128, b0 = blockIdx.y * 128, ks = blockIdx.z;
    int cbase = ks * NCH_;
    const char* pbase = (const char*)(d_Ph + (size_t)b0 * KE3_);
    const char* wbase = (const char*)(d_w2h + (size_t)g0 * KE3_);

    auto fill = [&](int cl, int s) {
        int c = cbase + cl;
        uint32_t asm_ = sb + s * STAGE_B;
        uint32_t bsm = asm_ + 16384;
        const char* psrc = pbase + (size_t)c * 128;
        const char* wsrc = wbase + (size_t)c * 128;
#pragma unroll
        for (int p = 0; p < 4; ++p) {
            int i = tid + p * 256;
            int row = i >> 3;
            int cb = (i & 7) << 4;
            uint32_t sw = SWZ(row * 128 + cb);
            cp16(asm_ + sw, psrc + (size_t)row * (KE3_ * 2) + cb);
            cp16(bsm + sw, wsrc + (size_t)row * (KE3_ * 2) + cb);
        }
    };

    float acc[4][4][4];
#pragma unroll
    for (int mt = 0; mt < 4; ++mt)
#pragma unroll
        for (int nt = 0; nt < 4; ++nt)
#pragma unroll
            for (int q = 0; q < 4; ++q) acc[mt][nt][q] = 0.f;

#pragma unroll
    for (int cl = 0; cl < GSTAGES - 1; ++cl) {
        fill(cl, cl);
        asm volatile("cp.async.commit_group;" ::: "memory");
    }

    for (int it = 0; it < NCH_; ++it) {
        asm volatile("cp.async.wait_group %0;" :: "n"(GSTAGES - 2) : "memory");
        __syncthreads();

        int cf = it + GSTAGES - 1;
        if (cf < NCH_) fill(cf, cf % GSTAGES);
        asm volatile("cp.async.commit_group;" ::: "memory");

        uint32_t As_u = sb + (it % GSTAGES) * STAGE_B;
        uint32_t Bs_u = As_u + 16384;

#pragma unroll
        for (int kst = 0; kst < 4; ++kst) {
            uint32_t af[4][4];
#pragma unroll
            for (int mt = 0; mt < 4; ++mt) {
                int row = wm * 64 + mt * 16 + rA;
                int byt = kst * 32 + bA;
                ldsm_x4(af[mt], As_u + row * 128 + (byt ^ ((row & 7) << 4)));
            }
            uint32_t bf[4][2];
#pragma unroll
            for (int p = 0; p < 2; ++p) {
                int row = wn * 32 + p * 16 + rB;
                int byt = kst * 32 + bB;
                uint32_t r[4];
                ldsm_x4(r, Bs_u + row * 128 + (byt ^ ((row & 7) << 4)));
                bf[2 * p][0] = r[0]; bf[2 * p][1] = r[1];
                bf[2 * p + 1][0] = r[2]; bf[2 * p + 1][1] = r[3];
            }
#pragma unroll
            for (int mt = 0; mt < 4; ++mt)
#pragma unroll
                for (int nt = 0; nt < 4; ++nt)
                    mma_f16(acc[mt][nt], af[mt], bf[nt]);
        }
    }

#pragma unroll
    for (int mt = 0; mt < 4; ++mt) {
#pragma unroll
        for (int nt = 0; nt < 4; ++nt) {
            int grow = b0 + wm * 64 + mt * 16 + row_l;
            int gcol = g0 + wn * 32 + nt * 8 + kq * 2;
            *(float2*)&d_c2[ks][grow][gcol]     = make_float2(acc[mt][nt][0], acc[mt][nt][1]);
            *(float2*)&d_c2[ks][grow + 8][gcol] = make_float2(acc[mt][nt][2], acc[mt][nt][3]);
        }
    }
}

// ---------------- final loss ----------------
__global__ void k_loss(const float* __restrict__ images, float* __restrict__ out) {
    int b = blockIdx.x, t = threadIdx.x;
    float s = 0.f;
    for (int g = t; g < 512; g += 128) {
        float v = -images[b * 512 + g];
#pragma unroll
        for (int h = 0; h < NSPLIT_; ++h) v += d_c2[h][b][g];
        s += v * v;
    }
    __shared__ float red[128];
    red[t] = s; __syncthreads();
    for (int q = 64; q; q >>= 1) { if (t < q) red[t] += red[t + q]; __syncthreads(); }
    if (t == 0) out[b] = red[0] * (1.f / 512.f);
}

// ---------------- launch: strictly sequential, default stream, no statics ----------------
extern "C" void kernel_launch(void* const* d_in, const int* in_sizes, int n_in,
                              void* d_out, int out_size) {
    const float* images = (const float*)d_in[0];
    const float* wimg   = (const float*)d_in[1];
    const float* wrec   = (const float*)d_in[2];
    const float* wrec2  = (const float*)d_in[3];
    const float* wimg2  = (const float*)d_in[4];
    float* out = (float*)d_out;

    cudaFuncSetAttribute(k_latlog2, cudaFuncAttributeMaxDynamicSharedMemorySize, SMEM_L2);
    cudaFuncSetAttribute(k_latlog4, cudaFuncAttributeMaxDynamicSharedMemorySize, SMEM_L4);
    cudaFuncSetAttribute(k_tgemm,   cudaFuncAttributeMaxDynamicSharedMemorySize, SMEM_G);

    k_prep1<<<dim3(65, 8), 256>>>(wimg, wimg2);
    k_qred<<<65, 256>>>();
    k_wnorm<<<8, 128>>>(wimg);
    k_norms<<<33, 256>>>(wrec, wrec2);
    k_log1t<<<dim3(8, NLS_), 256>>>(images, wimg);
    k_latlog2<<<128, 256, SMEM_L2>>>(wrec);
    k_dot2<<<B_, 256>>>(images);
    k_latlog4<<<128, 256, SMEM_L4>>>(wrec2);
    k_buildP<<<B_, 256>>>();
    k_tgemm<<<dim3(4, 8, NSPLIT_), 256, SMEM_G>>>();
    k_loss<<<B_, 128>>>(images, out);
}